// round 2
// baseline (speedup 1.0000x reference)
#include <cuda_runtime.h>
#include <math.h>

#define NN    50000
#define EE    1600000
#define HIGHD 4096
#define LOWD  64
#define EMB   128
#define HID   128
#define OUTC  10
#define BNEPS 1e-5f

// ---------------- scratch (static device memory; no allocations) ----------------
__device__ float g_Zh[(size_t)NN * EMB];   // relu(linear(bn(high_cov)))
__device__ float g_Zl[(size_t)NN * EMB];   // relu(linear(bn(low)))
__device__ float g_XW[(size_t)NN * HID];   // combined @ conv1_W (BN2 folded), incl const row
__device__ float g_W1h[HIGHD * EMB];
__device__ float g_c1h[EMB];
__device__ float g_W1l[LOWD * EMB];
__device__ float g_c1l[EMB];
__device__ float g_Wc[2 * EMB * HID];
__device__ float g_crow[HID];
__device__ float g_sum_h[HIGHD], g_ssq_h[HIGHD];
__device__ float g_sum_l[LOWD],  g_ssq_l[LOWD];
__device__ float g_scale_h[HIGHD], g_shift_h[HIGHD];
__device__ float g_scale_l[LOWD],  g_shift_l[LOWD];
__device__ float g_sum2[2 * EMB], g_ssq2[2 * EMB];     // [0:128) high-emb, [128:256) low-emb
__device__ float g_scale2[2 * EMB], g_shift2[2 * EMB];
__device__ int   g_deg[NN];
__device__ float g_dinv[NN];
__device__ int   g_rowoff[NN + 1];
__device__ int   g_cursor[NN];
__device__ int   g_csr[EE];
__device__ int   g_is64;

// ---------------- small utility kernels ----------------
__global__ void zero_kernel(int n) {
    int i = blockIdx.x * blockDim.x + threadIdx.x;
    if (i < HIGHD) { g_sum_h[i] = 0.f; g_ssq_h[i] = 0.f; }
    if (i < LOWD)  { g_sum_l[i] = 0.f; g_ssq_l[i] = 0.f; }
    if (i < 2 * EMB) { g_sum2[i] = 0.f; g_ssq2[i] = 0.f; }
    if (i < n) g_deg[i] = 0;
}

// detect whether edge_index is int64 (high words all zero) or int32
__global__ void detect_kernel(const int* __restrict__ edge_words, int e) {
    __shared__ int flag;
    if (threadIdx.x == 0) flag = 0;
    __syncthreads();
    int m = e < 1024 ? e : 1024;
    for (int i = threadIdx.x; i < m; i += blockDim.x) {
        if (edge_words[2 * i + 1] != 0) flag = 1;  // benign race
    }
    __syncthreads();
    if (threadIdx.x == 0) g_is64 = (flag ? 0 : 1);
}

// column sums / sum-of-squares of row-major [n, C]
__global__ void colstats_kernel(const float* __restrict__ x, int n, int C, int which) {
    float* sum = (which == 0) ? g_sum_h : g_sum_l;
    float* ssq = (which == 0) ? g_ssq_h : g_ssq_l;
    int c = blockIdx.x * blockDim.x + threadIdx.x;
    if (c >= C) return;
    float s = 0.f, q = 0.f;
    for (int r = blockIdx.y; r < n; r += gridDim.y) {
        float v = x[(size_t)r * C + c];
        s += v; q += v * v;
    }
    atomicAdd(&sum[c], s);
    atomicAdd(&ssq[c], q);
}

// scale = rsqrt(var+eps)*g ; shift = b - mean*scale
__global__ void finalize_kernel(const float* __restrict__ g, const float* __restrict__ b,
                                int C, float invn, int which) {
    const float *sum, *ssq; float *scale, *shift;
    if      (which == 0) { sum = g_sum_h;       ssq = g_ssq_h;       scale = g_scale_h;     shift = g_shift_h; }
    else if (which == 1) { sum = g_sum_l;       ssq = g_ssq_l;       scale = g_scale_l;     shift = g_shift_l; }
    else if (which == 2) { sum = g_sum2;        ssq = g_ssq2;        scale = g_scale2;      shift = g_shift2; }
    else                 { sum = g_sum2 + EMB;  ssq = g_ssq2 + EMB;  scale = g_scale2 + EMB; shift = g_shift2 + EMB; }
    int i = blockIdx.x * blockDim.x + threadIdx.x;
    if (i >= C) return;
    float m = sum[i] * invn;
    float var = ssq[i] * invn - m * m;
    float s = rsqrtf(var + BNEPS) * g[i];
    scale[i] = s;
    shift[i] = b[i] - m * s;
}

// W1[j][k] = W[j][k] * scale[j]   (out width = 128)
__global__ void foldW_kernel(const float* __restrict__ W, int total, int which) {
    const float* scale = (which == 0) ? g_scale_h : (which == 1) ? g_scale_l : g_scale2;
    float* W1          = (which == 0) ? g_W1h     : (which == 1) ? g_W1l     : g_Wc;
    int i = blockIdx.x * blockDim.x + threadIdx.x;
    if (i < total) W1[i] = W[i] * scale[i >> 7];
}

// c1[k] = linb[k] + sum_j shift[j]*W[j][k]
__global__ void foldbias_kernel(const float* __restrict__ W, const float* __restrict__ linb,
                                int K, int which) {
    const float* shift = (which == 0) ? g_shift_h : (which == 1) ? g_shift_l : g_shift2;
    float* c1          = (which == 0) ? g_c1h     : (which == 1) ? g_c1l     : g_crow;
    __shared__ float red[256];
    int k = blockIdx.x;
    float s = 0.f;
    for (int j = threadIdx.x; j < K; j += 256) s += shift[j] * W[(size_t)j * 128 + k];
    red[threadIdx.x] = s;
    __syncthreads();
    for (int off = 128; off; off >>= 1) {
        if ((int)threadIdx.x < off) red[threadIdx.x] += red[threadIdx.x + off];
        __syncthreads();
    }
    if (threadIdx.x == 0) c1[k] = (linb ? linb[k] : 0.f) + red[0];
}

// ---------------- GEMM 1: Z = relu(A[n,K] @ W1[K,128] + c1), accumulate col stats ----------------
__global__ __launch_bounds__(256) void gemm_relu_stats_kernel(
    const float* __restrict__ A, int n, int K, int sel)
{
    const float* B  = sel ? g_W1l : g_W1h;
    const float* c1 = sel ? g_c1l : g_c1h;
    float* Z        = sel ? g_Zl  : g_Zh;
    float* sumo     = sel ? (g_sum2 + EMB) : g_sum2;
    float* ssqo     = sel ? (g_ssq2 + EMB) : g_ssq2;

    __shared__ float As[16][128];
    __shared__ float Bs[16][128];
    const int tx = threadIdx.x;
    const int trow = tx >> 4, tcol = tx & 15;
    const int row0 = blockIdx.x * 128;

    float acc[8][8];
#pragma unroll
    for (int i = 0; i < 8; i++)
#pragma unroll
        for (int j = 0; j < 8; j++) acc[i][j] = 0.f;

    for (int k0 = 0; k0 < K; k0 += 16) {
#pragma unroll
        for (int i = 0; i < 2; i++) {
            int f = tx + i * 256;
            int r = f >> 2;
            int kc = (f & 3) << 2;
            int gr = row0 + r;
            float4 v = make_float4(0.f, 0.f, 0.f, 0.f);
            if (gr < n) v = *(const float4*)&A[(size_t)gr * K + k0 + kc];
            As[kc + 0][r] = v.x; As[kc + 1][r] = v.y; As[kc + 2][r] = v.z; As[kc + 3][r] = v.w;
        }
#pragma unroll
        for (int i = 0; i < 2; i++) {
            int f = tx + i * 256;
            int r = f >> 5;
            int cc = (f & 31) << 2;
            *(float4*)&Bs[r][cc] = *(const float4*)&B[(size_t)(k0 + r) * 128 + cc];
        }
        __syncthreads();
#pragma unroll
        for (int k = 0; k < 16; k++) {
            float a[8], b[8];
            *(float4*)&a[0] = *(const float4*)&As[k][trow * 8];
            *(float4*)&a[4] = *(const float4*)&As[k][trow * 8 + 4];
            *(float4*)&b[0] = *(const float4*)&Bs[k][tcol * 8];
            *(float4*)&b[4] = *(const float4*)&Bs[k][tcol * 8 + 4];
#pragma unroll
            for (int i = 0; i < 8; i++)
#pragma unroll
                for (int j = 0; j < 8; j++) acc[i][j] += a[i] * b[j];
        }
        __syncthreads();
    }

    float cs[8], cq[8], c1v[8];
#pragma unroll
    for (int j = 0; j < 8; j++) { cs[j] = 0.f; cq[j] = 0.f; c1v[j] = c1[tcol * 8 + j]; }
#pragma unroll
    for (int i = 0; i < 8; i++) {
        int gr = row0 + trow * 8 + i;
        if (gr < n) {
            float z[8];
#pragma unroll
            for (int j = 0; j < 8; j++) {
                float v = acc[i][j] + c1v[j];
                v = v > 0.f ? v : 0.f;
                z[j] = v; cs[j] += v; cq[j] += v * v;
            }
            *(float4*)&Z[(size_t)gr * 128 + tcol * 8]     = make_float4(z[0], z[1], z[2], z[3]);
            *(float4*)&Z[(size_t)gr * 128 + tcol * 8 + 4] = make_float4(z[4], z[5], z[6], z[7]);
        }
    }
    __syncthreads();
#pragma unroll
    for (int j = 0; j < 8; j++) As[trow][tcol * 8 + j] = cs[j];
    __syncthreads();
    if (tx < 128) {
        float s = 0.f;
#pragma unroll
        for (int r = 0; r < 16; r++) s += As[r][tx];
        atomicAdd(&sumo[tx], s);
    }
    __syncthreads();
#pragma unroll
    for (int j = 0; j < 8; j++) As[trow][tcol * 8 + j] = cq[j];
    __syncthreads();
    if (tx < 128) {
        float s = 0.f;
#pragma unroll
        for (int r = 0; r < 16; r++) s += As[r][tx];
        atomicAdd(&ssqo[tx], s);
    }
}

// ---------------- GEMM 2: XW = [Zh|Zl] @ Wc[256,128] + crow ----------------
__global__ __launch_bounds__(256) void gemm2_kernel(int n) {
    __shared__ float As[16][128];
    __shared__ float Bs[16][128];
    const int tx = threadIdx.x;
    const int trow = tx >> 4, tcol = tx & 15;
    const int row0 = blockIdx.x * 128;

    float acc[8][8];
#pragma unroll
    for (int i = 0; i < 8; i++)
#pragma unroll
        for (int j = 0; j < 8; j++) acc[i][j] = 0.f;

    for (int k0 = 0; k0 < 256; k0 += 16) {
        const float* Asrc = (k0 < 128) ? g_Zh : g_Zl;
        int kk = k0 & 127;
#pragma unroll
        for (int i = 0; i < 2; i++) {
            int f = tx + i * 256;
            int r = f >> 2;
            int kc = (f & 3) << 2;
            int gr = row0 + r;
            float4 v = make_float4(0.f, 0.f, 0.f, 0.f);
            if (gr < n) v = *(const float4*)&Asrc[(size_t)gr * 128 + kk + kc];
            As[kc + 0][r] = v.x; As[kc + 1][r] = v.y; As[kc + 2][r] = v.z; As[kc + 3][r] = v.w;
        }
#pragma unroll
        for (int i = 0; i < 2; i++) {
            int f = tx + i * 256;
            int r = f >> 5;
            int cc = (f & 31) << 2;
            *(float4*)&Bs[r][cc] = *(const float4*)&g_Wc[(size_t)(k0 + r) * 128 + cc];
        }
        __syncthreads();
#pragma unroll
        for (int k = 0; k < 16; k++) {
            float a[8], b[8];
            *(float4*)&a[0] = *(const float4*)&As[k][trow * 8];
            *(float4*)&a[4] = *(const float4*)&As[k][trow * 8 + 4];
            *(float4*)&b[0] = *(const float4*)&Bs[k][tcol * 8];
            *(float4*)&b[4] = *(const float4*)&Bs[k][tcol * 8 + 4];
#pragma unroll
            for (int i = 0; i < 8; i++)
#pragma unroll
                for (int j = 0; j < 8; j++) acc[i][j] += a[i] * b[j];
        }
        __syncthreads();
    }
    float cr[8];
#pragma unroll
    for (int j = 0; j < 8; j++) cr[j] = g_crow[tcol * 8 + j];
#pragma unroll
    for (int i = 0; i < 8; i++) {
        int gr = row0 + trow * 8 + i;
        if (gr < n) {
            float z[8];
#pragma unroll
            for (int j = 0; j < 8; j++) z[j] = acc[i][j] + cr[j];
            *(float4*)&g_XW[(size_t)gr * 128 + tcol * 8]     = make_float4(z[0], z[1], z[2], z[3]);
            *(float4*)&g_XW[(size_t)gr * 128 + tcol * 8 + 4] = make_float4(z[4], z[5], z[6], z[7]);
        }
    }
}

// ---------------- graph machinery ----------------
__device__ __forceinline__ int edge_at(const void* edge, int e, int which_row, int i) {
    if (g_is64) {
        const long long* p = (const long long*)edge;
        return (int)p[(size_t)which_row * e + i];
    } else {
        const int* p = (const int*)edge;
        return p[(size_t)which_row * e + i];
    }
}

__global__ void deg_kernel(const void* __restrict__ edge, int e) {
    for (int i = blockIdx.x * blockDim.x + threadIdx.x; i < e; i += gridDim.x * blockDim.x) {
        int d = edge_at(edge, e, 1, i);
        atomicAdd(&g_deg[d], 1);
    }
}

__global__ void dinv_kernel(int n) {
    int i = blockIdx.x * blockDim.x + threadIdx.x;
    if (i < n) g_dinv[i] = rsqrtf((float)(g_deg[i] + 1));  // +1 self loop
}

__global__ void scan_kernel(int n) {
    __shared__ int sh[1024];
    __shared__ int carry_s;
    int tx = threadIdx.x;
    if (tx == 0) { carry_s = 0; g_rowoff[0] = 0; }
    __syncthreads();
    for (int base = 0; base < n; base += 1024) {
        int i = base + tx;
        int v = (i < n) ? g_deg[i] : 0;
        sh[tx] = v;
        __syncthreads();
        for (int off = 1; off < 1024; off <<= 1) {
            int t = (tx >= off) ? sh[tx - off] : 0;
            __syncthreads();
            sh[tx] += t;
            __syncthreads();
        }
        int carry = carry_s;
        if (i < n) {
            g_rowoff[i + 1] = sh[tx] + carry;
            g_cursor[i] = sh[tx] - v + carry;
        }
        __syncthreads();
        if (tx == 0) carry_s = carry + sh[1023];
        __syncthreads();
    }
}

__global__ void fill_kernel(const void* __restrict__ edge, int e) {
    for (int i = blockIdx.x * blockDim.x + threadIdx.x; i < e; i += gridDim.x * blockDim.x) {
        int d = edge_at(edge, e, 1, i);
        int s = edge_at(edge, e, 0, i);
        int p = atomicAdd(&g_cursor[d], 1);
        g_csr[p] = s;
    }
}

// ---------------- gather + tanh + classifier + log_softmax ----------------
__global__ void gather_kernel(const float* __restrict__ convb, const float* __restrict__ clsW,
                              const float* __restrict__ clsb, float* __restrict__ out, int n)
{
    int gw = (blockIdx.x * blockDim.x + threadIdx.x) >> 5;
    int lane = threadIdx.x & 31;
    if (gw >= n) return;
    const float di = g_dinv[gw];
    const float4* xw4 = (const float4*)g_XW;

    float4 a = xw4[(size_t)gw * 32 + lane];  // self loop (norm = di*di, one di applied at end)
    float ax = a.x * di, ay = a.y * di, az = a.z * di, aw = a.w * di;

    int beg = g_rowoff[gw], end = g_rowoff[gw + 1];
    for (int j = beg; j < end; j++) {
        int s = g_csr[j];
        float w = g_dinv[s];
        float4 v = xw4[(size_t)s * 32 + lane];
        ax += v.x * w; ay += v.y * w; az += v.z * w; aw += v.w * w;
    }
    float4 cb = ((const float4*)convb)[lane];
    float h0 = tanhf(ax * di + cb.x);
    float h1 = tanhf(ay * di + cb.y);
    float h2 = tanhf(az * di + cb.z);
    float h3 = tanhf(aw * di + cb.w);

    int c0 = lane * 4;
    float lo[OUTC];
#pragma unroll
    for (int o = 0; o < OUTC; o++) {
        lo[o] = h0 * clsW[(size_t)c0 * OUTC + o]
              + h1 * clsW[(size_t)(c0 + 1) * OUTC + o]
              + h2 * clsW[(size_t)(c0 + 2) * OUTC + o]
              + h3 * clsW[(size_t)(c0 + 3) * OUTC + o];
    }
#pragma unroll
    for (int off = 16; off; off >>= 1)
#pragma unroll
        for (int o = 0; o < OUTC; o++)
            lo[o] += __shfl_xor_sync(0xffffffffu, lo[o], off);

    if (lane == 0) {
        float m = -1e30f;
#pragma unroll
        for (int o = 0; o < OUTC; o++) { lo[o] += clsb[o]; m = fmaxf(m, lo[o]); }
        float s = 0.f;
#pragma unroll
        for (int o = 0; o < OUTC; o++) s += expf(lo[o] - m);
        float lse = m + logf(s);
#pragma unroll
        for (int o = 0; o < OUTC; o++) out[(size_t)gw * OUTC + o] = lo[o] - lse;
    }
}

// ---------------- launch ----------------
extern "C" void kernel_launch(void* const* d_in, const int* in_sizes, int n_in,
                              void* d_out, int out_size) {
    const float* low_x      = (const float*)d_in[1];
    const float* cov_x      = (const float*)d_in[2];
    const void*  edge       = d_in[3];
    const float* bn_low_g   = (const float*)d_in[4];
    const float* bn_low_b   = (const float*)d_in[5];
    const float* bn_high_g  = (const float*)d_in[6];
    const float* bn_high_b  = (const float*)d_in[7];
    const float* lin_low_W  = (const float*)d_in[8];
    const float* lin_low_b  = (const float*)d_in[9];
    const float* mlp_low_g  = (const float*)d_in[10];
    const float* mlp_low_b  = (const float*)d_in[11];
    const float* lin_high_W = (const float*)d_in[12];
    const float* lin_high_b = (const float*)d_in[13];
    const float* mlp_high_g = (const float*)d_in[14];
    const float* mlp_high_b = (const float*)d_in[15];
    const float* conv1_W    = (const float*)d_in[16];
    const float* conv1_b    = (const float*)d_in[17];
    const float* cls_W      = (const float*)d_in[18];
    const float* cls_b      = (const float*)d_in[19];

    int n = in_sizes[1] / LOWD;
    int e = in_sizes[3] / 2;
    float invn = 1.f / (float)n;
    int nblk = (n + 127) / 128;

    zero_kernel<<<(n + 255) / 256, 256>>>(n);
    detect_kernel<<<1, 256>>>((const int*)edge, e);

    // pass 1: input BN stats
    colstats_kernel<<<dim3(HIGHD / 256, 256), 256>>>(cov_x, n, HIGHD, 0);
    colstats_kernel<<<dim3(1, 256), 256>>>(low_x, n, LOWD, 1);
    finalize_kernel<<<HIGHD / 256, 256>>>(bn_high_g, bn_high_b, HIGHD, invn, 0);
    finalize_kernel<<<1, LOWD>>>(bn_low_g, bn_low_b, LOWD, invn, 1);

    // fold BN1 into linears
    foldW_kernel<<<(HIGHD * EMB) / 256, 256>>>(lin_high_W, HIGHD * EMB, 0);
    foldbias_kernel<<<EMB, 256>>>(lin_high_W, lin_high_b, HIGHD, 0);
    foldW_kernel<<<(LOWD * EMB) / 256, 256>>>(lin_low_W, LOWD * EMB, 1);
    foldbias_kernel<<<EMB, 256>>>(lin_low_W, lin_low_b, LOWD, 1);

    // pass 2: GEMMs + relu + post-relu stats
    gemm_relu_stats_kernel<<<nblk, 256>>>(cov_x, n, HIGHD, 0);
    gemm_relu_stats_kernel<<<nblk, 256>>>(low_x, n, LOWD, 1);

    // fold BN2 into conv1_W
    finalize_kernel<<<1, EMB>>>(mlp_high_g, mlp_high_b, EMB, invn, 2);
    finalize_kernel<<<1, EMB>>>(mlp_low_g, mlp_low_b, EMB, invn, 3);
    foldW_kernel<<<(2 * EMB * HID) / 256, 256>>>(conv1_W, 2 * EMB * HID, 2);
    foldbias_kernel<<<HID, 256>>>(conv1_W, (const float*)0, 2 * EMB, 2);

    // xw = combined @ conv1_W
    gemm2_kernel<<<nblk, 256>>>(n);

    // graph: degree -> dinv -> CSR
    deg_kernel<<<2048, 256>>>(edge, e);
    dinv_kernel<<<(n + 255) / 256, 256>>>(n);
    scan_kernel<<<1, 1024>>>(n);
    fill_kernel<<<2048, 256>>>(edge, e);

    // aggregate + tanh + classifier + log_softmax
    gather_kernel<<<(n * 32 + 255) / 256, 256>>>(conv1_b, cls_W, cls_b, (float*)d_out, n);
}

// round 5
// speedup vs baseline: 1.7533x; 1.7533x over previous
#include <cuda_runtime.h>
#include <cuda_bf16.h>
#include <math.h>
#include <stdint.h>

#define NN    50000
#define EE    1600000
#define HIGHD 4096
#define LOWD  64
#define EMB   128
#define HID   128
#define OUTC  10
#define BNEPS 1e-5f
#define KCH   32
#define NCHUNK (HIGHD / KCH)   // 128

// ---------------- scratch (static device memory; no allocations) ----------------
__device__ float g_Zh[(size_t)NN * EMB];
__device__ float g_Zl[(size_t)NN * EMB];
__device__ float g_XW[(size_t)NN * HID];
__device__ __nv_bfloat16 g_Bhi[(size_t)HIGHD * EMB];   // W1h^T bf16-hi, pre-swizzled [chunk][n][k]
__device__ __nv_bfloat16 g_Blo[(size_t)HIGHD * EMB];   // bf16-lo residual
__device__ float g_c1h[EMB];
__device__ float g_W1l[LOWD * EMB];
__device__ float g_c1l[EMB];
__device__ float g_Wc[2 * EMB * HID];
__device__ float g_crow[HID];
__device__ float g_sum_h[HIGHD], g_ssq_h[HIGHD];
__device__ float g_sum_l[LOWD],  g_ssq_l[LOWD];
__device__ float g_scale_h[HIGHD], g_shift_h[HIGHD];
__device__ float g_scale_l[LOWD],  g_shift_l[LOWD];
__device__ float g_sum2[2 * EMB], g_ssq2[2 * EMB];
__device__ float g_scale2[2 * EMB], g_shift2[2 * EMB];
__device__ int   g_deg[NN];
__device__ float g_dinv[NN];
__device__ int   g_rowoff[NN + 1];
__device__ int   g_cursor[NN];
__device__ int   g_csr[EE];
__device__ int   g_is64;

// ---------------- PTX helpers (portable: ldmatrix sm_75+, mma.sync bf16 sm_80+) ----------------
__device__ __forceinline__ uint32_t smem_u32(const void* p) {
    uint32_t a;
    asm("{ .reg .u64 t; cvta.to.shared.u64 t, %1; cvt.u32.u64 %0, t; }" : "=r"(a) : "l"(p));
    return a;
}
#define LDMX4(r, a) \
    asm volatile("ldmatrix.sync.aligned.m8n8.x4.shared.b16 {%0,%1,%2,%3}, [%4];" \
        : "=r"((r)[0]), "=r"((r)[1]), "=r"((r)[2]), "=r"((r)[3]) : "r"(a))

__device__ __forceinline__ void mma_bf16(float* c, const uint32_t* a, uint32_t b0, uint32_t b1) {
    asm volatile(
        "mma.sync.aligned.m16n8k16.row.col.f32.bf16.bf16.f32 "
        "{%0,%1,%2,%3}, {%4,%5,%6,%7}, {%8,%9}, {%0,%1,%2,%3};"
        : "+f"(c[0]), "+f"(c[1]), "+f"(c[2]), "+f"(c[3])
        : "r"(a[0]), "r"(a[1]), "r"(a[2]), "r"(a[3]), "r"(b0), "r"(b1));
}

// ---------------- small utility kernels ----------------
__global__ void zero_kernel(int n) {
    int i = blockIdx.x * blockDim.x + threadIdx.x;
    if (i < HIGHD) { g_sum_h[i] = 0.f; g_ssq_h[i] = 0.f; }
    if (i < LOWD)  { g_sum_l[i] = 0.f; g_ssq_l[i] = 0.f; }
    if (i < 2 * EMB) { g_sum2[i] = 0.f; g_ssq2[i] = 0.f; }
    if (i < n) g_deg[i] = 0;
}

__global__ void detect_kernel(const int* __restrict__ edge_words, int e) {
    __shared__ int flag;
    if (threadIdx.x == 0) flag = 0;
    __syncthreads();
    int m = e < 1024 ? e : 1024;
    for (int i = threadIdx.x; i < m; i += blockDim.x)
        if (edge_words[2 * i + 1] != 0) flag = 1;
    __syncthreads();
    if (threadIdx.x == 0) g_is64 = (flag ? 0 : 1);
}

// coalesced column stats: block = 64 cols x 4 rows
__global__ void colstats2_kernel(const float* __restrict__ x, int n, int C, int which) {
    float* sum = (which == 0) ? g_sum_h : g_sum_l;
    float* ssq = (which == 0) ? g_ssq_h : g_ssq_l;
    int c = blockIdx.x * 64 + (threadIdx.x & 63);
    int rofs = threadIdx.x >> 6;
    float s = 0.f, q = 0.f;
    for (int r = blockIdx.y * 4 + rofs; r < n; r += gridDim.y * 4) {
        float v = x[(size_t)r * C + c];
        s += v; q += v * v;
    }
    __shared__ float sh[2][256];
    sh[0][threadIdx.x] = s; sh[1][threadIdx.x] = q;
    __syncthreads();
    if (threadIdx.x < 64) {
        float S = sh[0][threadIdx.x] + sh[0][threadIdx.x + 64] + sh[0][threadIdx.x + 128] + sh[0][threadIdx.x + 192];
        float Q = sh[1][threadIdx.x] + sh[1][threadIdx.x + 64] + sh[1][threadIdx.x + 128] + sh[1][threadIdx.x + 192];
        atomicAdd(&sum[c], S); atomicAdd(&ssq[c], Q);
    }
}

__global__ void finalize_kernel(const float* __restrict__ g, const float* __restrict__ b,
                                int C, float invn, int which) {
    const float *sum, *ssq; float *scale, *shift;
    if      (which == 0) { sum = g_sum_h;      ssq = g_ssq_h;      scale = g_scale_h;      shift = g_shift_h; }
    else if (which == 1) { sum = g_sum_l;      ssq = g_ssq_l;      scale = g_scale_l;      shift = g_shift_l; }
    else if (which == 2) { sum = g_sum2;       ssq = g_ssq2;       scale = g_scale2;       shift = g_shift2; }
    else                 { sum = g_sum2 + EMB; ssq = g_ssq2 + EMB; scale = g_scale2 + EMB; shift = g_shift2 + EMB; }
    int i = blockIdx.x * blockDim.x + threadIdx.x;
    if (i >= C) return;
    float m = sum[i] * invn;
    float var = ssq[i] * invn - m * m;
    float s = rsqrtf(var + BNEPS) * g[i];
    scale[i] = s;
    shift[i] = b[i] - m * s;
}

__global__ void foldW_kernel(const float* __restrict__ W, int total, int which) {
    const float* scale = (which == 1) ? g_scale_l : g_scale2;
    float* W1          = (which == 1) ? g_W1l     : g_Wc;
    int i = blockIdx.x * blockDim.x + threadIdx.x;
    if (i < total) W1[i] = W[i] * scale[i >> 7];
}

// high weight fold: transpose to [n][k] k-major bf16 hi/lo, per-32k chunk, swizzled rows
// swizzle: within a 64B row, 16B unit ^= (row>>1)&3  -> conflict-free ldmatrix
__global__ void foldWt_kernel(const float* __restrict__ W) {
    int i = blockIdx.x * blockDim.x + threadIdx.x;
    if (i >= HIGHD * EMB) return;
    int k = i >> 7, nn = i & 127;
    float v = W[i] * g_scale_h[k];
    __nv_bfloat16 h = __float2bfloat16(v);
    __nv_bfloat16 l = __float2bfloat16(v - __bfloat162float(h));
    int c = k >> 5, kk = k & 31;
    uint32_t kb = (uint32_t)kk * 2;
    uint32_t sw = ((kb & 0x30u) ^ (((uint32_t)(nn >> 1) & 3u) << 4)) | (kb & 15u);
    size_t idx = (size_t)c * 4096 + (((uint32_t)nn * 64 + sw) >> 1);
    g_Bhi[idx] = h; g_Blo[idx] = l;
}

__global__ void foldbias_kernel(const float* __restrict__ W, const float* __restrict__ linb,
                                int K, int which) {
    const float* shift = (which == 0) ? g_shift_h : (which == 1) ? g_shift_l : g_shift2;
    float* c1          = (which == 0) ? g_c1h     : (which == 1) ? g_c1l     : g_crow;
    __shared__ float red[256];
    int k = blockIdx.x;
    float s = 0.f;
    for (int j = threadIdx.x; j < K; j += 256) s += shift[j] * W[(size_t)j * 128 + k];
    red[threadIdx.x] = s;
    __syncthreads();
    for (int off = 128; off; off >>= 1) {
        if ((int)threadIdx.x < off) red[threadIdx.x] += red[threadIdx.x + off];
        __syncthreads();
    }
    if (threadIdx.x == 0) c1[k] = (linb ? linb[k] : 0.f) + red[0];
}

// ---------------- high-path GEMM via mma.sync bf16-split: Z = relu(A@W1h + c1h) + stats ----------------
__global__ void __launch_bounds__(256, 2) gemm_mma_kernel(const float* __restrict__ A, int n) {
    __shared__ __align__(16) __nv_bfloat16 sAhi[128 * 32];
    __shared__ __align__(16) __nv_bfloat16 sAlo[128 * 32];
    __shared__ __align__(16) __nv_bfloat16 sBhi[128 * 32];
    __shared__ __align__(16) __nv_bfloat16 sBlo[128 * 32];
    __shared__ float ssum[128], ssqs[128];

    const int tid = threadIdx.x;
    const int wid = tid >> 5, lane = tid & 31;
    const int wm = wid & 3;        // m offset wm*32
    const int wn = wid >> 2;       // n offset wn*64
    const int row0 = blockIdx.x * 128;

    if (tid < 128) { ssum[tid] = 0.f; ssqs[tid] = 0.f; }

    // producer mapping: thread handles row prow, 16 consecutive k floats
    const int prow = tid >> 1;
    const int pk   = (tid & 1) * 16;
    const bool avalid = (row0 + prow) < n;
    const float* aptr = A + (size_t)(row0 + prow) * HIGHD + pk;
    const uint32_t swxP = (((uint32_t)(prow >> 1) & 3u) << 4);
    char* sAh8 = (char*)sAhi + prow * 64;
    char* sAl8 = (char*)sAlo + prow * 64;

    const uint4* Bh4 = (const uint4*)g_Bhi;
    const uint4* Bl4 = (const uint4*)g_Blo;

    // consumer ldmatrix address parts
    const uint32_t aB = smem_u32(sAhi), aBl = smem_u32(sAlo);
    const uint32_t bB = smem_u32(sBhi), bBl = smem_u32(sBlo);
    const int lrA = lane & 15;
    const uint32_t lkA = ((uint32_t)(lane >> 4)) << 4;
    const uint32_t swA = (((uint32_t)(lrA >> 1) & 3u) << 4);
    const int lrB = (lane & 7) + ((lane >> 4) << 3);
    const uint32_t lkB = ((uint32_t)(lane & 8)) << 1;
    const uint32_t swB = (((uint32_t)(lrB >> 1) & 3u) << 4);

    float acc[2][8][4];
#pragma unroll
    for (int mt = 0; mt < 2; mt++)
#pragma unroll
        for (int j = 0; j < 8; j++)
#pragma unroll
            for (int q = 0; q < 4; q++) acc[mt][j][q] = 0.f;

    // prefetch chunk 0
    float4 ar[4];
    uint4 bh[2], bl[2];
#pragma unroll
    for (int i = 0; i < 4; i++)
        ar[i] = avalid ? *(const float4*)(aptr + i * 4) : make_float4(0.f, 0.f, 0.f, 0.f);
#pragma unroll
    for (int j = 0; j < 2; j++) { bh[j] = Bh4[tid + j * 256]; bl[j] = Bl4[tid + j * 256]; }

    for (int c = 0; c < NCHUNK; c++) {
        __syncthreads();   // previous chunk's consumers done
        // store A (convert to bf16 hi/lo, swizzled)
#pragma unroll
        for (int i = 0; i < 4; i++) {
            float4 a = ar[i];
            __nv_bfloat16 h0 = __float2bfloat16(a.x), h1 = __float2bfloat16(a.y);
            __nv_bfloat16 h2 = __float2bfloat16(a.z), h3 = __float2bfloat16(a.w);
            __nv_bfloat16 l0 = __float2bfloat16(a.x - __bfloat162float(h0));
            __nv_bfloat16 l1 = __float2bfloat16(a.y - __bfloat162float(h1));
            __nv_bfloat16 l2 = __float2bfloat16(a.z - __bfloat162float(h2));
            __nv_bfloat16 l3 = __float2bfloat16(a.w - __bfloat162float(h3));
            uint32_t hA = (uint32_t)__bfloat16_as_ushort(h0) | ((uint32_t)__bfloat16_as_ushort(h1) << 16);
            uint32_t hB = (uint32_t)__bfloat16_as_ushort(h2) | ((uint32_t)__bfloat16_as_ushort(h3) << 16);
            uint32_t lA = (uint32_t)__bfloat16_as_ushort(l0) | ((uint32_t)__bfloat16_as_ushort(l1) << 16);
            uint32_t lB = (uint32_t)__bfloat16_as_ushort(l2) | ((uint32_t)__bfloat16_as_ushort(l3) << 16);
            uint32_t kb = (uint32_t)(pk * 2 + i * 8);
            uint32_t so = kb ^ swxP;          // swizzle touches bits 4-5 only
            *(uint2*)(sAh8 + so) = make_uint2(hA, hB);
            *(uint2*)(sAl8 + so) = make_uint2(lA, lB);
        }
        // store B (pre-swizzled, straight copy)
#pragma unroll
        for (int j = 0; j < 2; j++) {
            ((uint4*)sBhi)[tid + j * 256] = bh[j];
            ((uint4*)sBlo)[tid + j * 256] = bl[j];
        }
        __syncthreads();

        // prefetch next chunk (overlaps mma work)
        if (c + 1 < NCHUNK) {
#pragma unroll
            for (int i = 0; i < 4; i++)
                ar[i] = avalid ? *(const float4*)(aptr + (c + 1) * KCH + i * 4)
                               : make_float4(0.f, 0.f, 0.f, 0.f);
#pragma unroll
            for (int j = 0; j < 2; j++) {
                bh[j] = Bh4[(size_t)(c + 1) * 512 + tid + j * 256];
                bl[j] = Bl4[(size_t)(c + 1) * 512 + tid + j * 256];
            }
        }

        // compute: 2 k16 steps
#pragma unroll
        for (int ks = 0; ks < 2; ks++) {
            uint32_t ahi[2][4], alo[2][4];
#pragma unroll
            for (int mt = 0; mt < 2; mt++) {
                uint32_t off = (uint32_t)(wm * 32 + mt * 16 + lrA) * 64 +
                               (((uint32_t)(ks * 32) + lkA) ^ swA);
                LDMX4(ahi[mt], aB + off);
                LDMX4(alo[mt], aBl + off);
            }
#pragma unroll
            for (int g4 = 0; g4 < 4; g4++) {
                uint32_t boff = (uint32_t)(wn * 64 + g4 * 16 + lrB) * 64 +
                                (((uint32_t)(ks * 32) + lkB) ^ swB);
                uint32_t bhf[4], blf[4];
                LDMX4(bhf, bB + boff);
                LDMX4(blf, bBl + boff);
#pragma unroll
                for (int mt = 0; mt < 2; mt++) {
                    mma_bf16(acc[mt][g4 * 2 + 0], ahi[mt], bhf[0], bhf[1]);
                    mma_bf16(acc[mt][g4 * 2 + 1], ahi[mt], bhf[2], bhf[3]);
                    mma_bf16(acc[mt][g4 * 2 + 0], ahi[mt], blf[0], blf[1]);
                    mma_bf16(acc[mt][g4 * 2 + 1], ahi[mt], blf[2], blf[3]);
                    mma_bf16(acc[mt][g4 * 2 + 0], alo[mt], bhf[0], bhf[1]);
                    mma_bf16(acc[mt][g4 * 2 + 1], alo[mt], bhf[2], bhf[3]);
                }
            }
        }
    }

    // epilogue: bias + relu + store Z + BN2 column stats
    const int g = lane >> 2, t4 = lane & 3;
#pragma unroll
    for (int j = 0; j < 8; j++) {
        int col = wn * 64 + j * 8 + t4 * 2;
        float c1a = g_c1h[col], c1b = g_c1h[col + 1];
        float sa = 0.f, sb = 0.f, qa = 0.f, qb = 0.f;
#pragma unroll
        for (int mt = 0; mt < 2; mt++) {
            int r0 = row0 + wm * 32 + mt * 16 + g;
            int r1 = r0 + 8;
            float x0 = fmaxf(acc[mt][j][0] + c1a, 0.f);
            float x1 = fmaxf(acc[mt][j][1] + c1b, 0.f);
            float x2 = fmaxf(acc[mt][j][2] + c1a, 0.f);
            float x3 = fmaxf(acc[mt][j][3] + c1b, 0.f);
            if (r0 < n) {
                *(float2*)&g_Zh[(size_t)r0 * 128 + col] = make_float2(x0, x1);
                sa += x0; sb += x1; qa += x0 * x0; qb += x1 * x1;
            }
            if (r1 < n) {
                *(float2*)&g_Zh[(size_t)r1 * 128 + col] = make_float2(x2, x3);
                sa += x2; sb += x3; qa += x2 * x2; qb += x3 * x3;
            }
        }
        atomicAdd(&ssum[col], sa); atomicAdd(&ssum[col + 1], sb);
        atomicAdd(&ssqs[col], qa); atomicAdd(&ssqs[col + 1], qb);
    }
    __syncthreads();
    if (tid < 128) {
        atomicAdd(&g_sum2[tid], ssum[tid]);
        atomicAdd(&g_ssq2[tid], ssqs[tid]);
    }
}

// ---------------- low-path SIMT GEMM (K=64): Z = relu(A@W1l + c1l) + stats ----------------
__global__ __launch_bounds__(256) void gemm_relu_stats_kernel(const float* __restrict__ A, int n) {
    const float* B  = g_W1l;
    const float* c1 = g_c1l;
    float* Z        = g_Zl;
    float* sumo     = g_sum2 + EMB;
    float* ssqo     = g_ssq2 + EMB;

    __shared__ float As[16][128];
    __shared__ float Bs[16][128];
    const int tx = threadIdx.x;
    const int trow = tx >> 4, tcol = tx & 15;
    const int row0 = blockIdx.x * 128;

    float acc[8][8];
#pragma unroll
    for (int i = 0; i < 8; i++)
#pragma unroll
        for (int j = 0; j < 8; j++) acc[i][j] = 0.f;

    for (int k0 = 0; k0 < LOWD; k0 += 16) {
#pragma unroll
        for (int i = 0; i < 2; i++) {
            int f = tx + i * 256;
            int r = f >> 2;
            int kc = (f & 3) << 2;
            int gr = row0 + r;
            float4 v = make_float4(0.f, 0.f, 0.f, 0.f);
            if (gr < n) v = *(const float4*)&A[(size_t)gr * LOWD + k0 + kc];
            As[kc + 0][r] = v.x; As[kc + 1][r] = v.y; As[kc + 2][r] = v.z; As[kc + 3][r] = v.w;
        }
#pragma unroll
        for (int i = 0; i < 2; i++) {
            int f = tx + i * 256;
            int r = f >> 5;
            int cc = (f & 31) << 2;
            *(float4*)&Bs[r][cc] = *(const float4*)&B[(size_t)(k0 + r) * 128 + cc];
        }
        __syncthreads();
#pragma unroll
        for (int k = 0; k < 16; k++) {
            float a[8], b[8];
            *(float4*)&a[0] = *(const float4*)&As[k][trow * 8];
            *(float4*)&a[4] = *(const float4*)&As[k][trow * 8 + 4];
            *(float4*)&b[0] = *(const float4*)&Bs[k][tcol * 8];
            *(float4*)&b[4] = *(const float4*)&Bs[k][tcol * 8 + 4];
#pragma unroll
            for (int i = 0; i < 8; i++)
#pragma unroll
                for (int j = 0; j < 8; j++) acc[i][j] += a[i] * b[j];
        }
        __syncthreads();
    }

    float cs[8], cq[8], c1v[8];
#pragma unroll
    for (int j = 0; j < 8; j++) { cs[j] = 0.f; cq[j] = 0.f; c1v[j] = c1[tcol * 8 + j]; }
#pragma unroll
    for (int i = 0; i < 8; i++) {
        int gr = row0 + trow * 8 + i;
        if (gr < n) {
            float z[8];
#pragma unroll
            for (int j = 0; j < 8; j++) {
                float v = acc[i][j] + c1v[j];
                v = v > 0.f ? v : 0.f;
                z[j] = v; cs[j] += v; cq[j] += v * v;
            }
            *(float4*)&Z[(size_t)gr * 128 + tcol * 8]     = make_float4(z[0], z[1], z[2], z[3]);
            *(float4*)&Z[(size_t)gr * 128 + tcol * 8 + 4] = make_float4(z[4], z[5], z[6], z[7]);
        }
    }
    __syncthreads();
#pragma unroll
    for (int j = 0; j < 8; j++) As[trow][tcol * 8 + j] = cs[j];
    __syncthreads();
    if (tx < 128) {
        float s = 0.f;
#pragma unroll
        for (int r = 0; r < 16; r++) s += As[r][tx];
        atomicAdd(&sumo[tx], s);
    }
    __syncthreads();
#pragma unroll
    for (int j = 0; j < 8; j++) As[trow][tcol * 8 + j] = cq[j];
    __syncthreads();
    if (tx < 128) {
        float s = 0.f;
#pragma unroll
        for (int r = 0; r < 16; r++) s += As[r][tx];
        atomicAdd(&ssqo[tx], s);
    }
}

// ---------------- GEMM 2: XW = [Zh|Zl] @ Wc[256,128] + crow ----------------
__global__ __launch_bounds__(256) void gemm2_kernel(int n) {
    __shared__ float As[16][128];
    __shared__ float Bs[16][128];
    const int tx = threadIdx.x;
    const int trow = tx >> 4, tcol = tx & 15;
    const int row0 = blockIdx.x * 128;

    float acc[8][8];
#pragma unroll
    for (int i = 0; i < 8; i++)
#pragma unroll
        for (int j = 0; j < 8; j++) acc[i][j] = 0.f;

    for (int k0 = 0; k0 < 256; k0 += 16) {
        const float* Asrc = (k0 < 128) ? g_Zh : g_Zl;
        int kk = k0 & 127;
#pragma unroll
        for (int i = 0; i < 2; i++) {
            int f = tx + i * 256;
            int r = f >> 2;
            int kc = (f & 3) << 2;
            int gr = row0 + r;
            float4 v = make_float4(0.f, 0.f, 0.f, 0.f);
            if (gr < n) v = *(const float4*)&Asrc[(size_t)gr * 128 + kk + kc];
            As[kc + 0][r] = v.x; As[kc + 1][r] = v.y; As[kc + 2][r] = v.z; As[kc + 3][r] = v.w;
        }
#pragma unroll
        for (int i = 0; i < 2; i++) {
            int f = tx + i * 256;
            int r = f >> 5;
            int cc = (f & 31) << 2;
            *(float4*)&Bs[r][cc] = *(const float4*)&g_Wc[(size_t)(k0 + r) * 128 + cc];
        }
        __syncthreads();
#pragma unroll
        for (int k = 0; k < 16; k++) {
            float a[8], b[8];
            *(float4*)&a[0] = *(const float4*)&As[k][trow * 8];
            *(float4*)&a[4] = *(const float4*)&As[k][trow * 8 + 4];
            *(float4*)&b[0] = *(const float4*)&Bs[k][tcol * 8];
            *(float4*)&b[4] = *(const float4*)&Bs[k][tcol * 8 + 4];
#pragma unroll
            for (int i = 0; i < 8; i++)
#pragma unroll
                for (int j = 0; j < 8; j++) acc[i][j] += a[i] * b[j];
        }
        __syncthreads();
    }
    float cr[8];
#pragma unroll
    for (int j = 0; j < 8; j++) cr[j] = g_crow[tcol * 8 + j];
#pragma unroll
    for (int i = 0; i < 8; i++) {
        int gr = row0 + trow * 8 + i;
        if (gr < n) {
            float z[8];
#pragma unroll
            for (int j = 0; j < 8; j++) z[j] = acc[i][j] + cr[j];
            *(float4*)&g_XW[(size_t)gr * 128 + tcol * 8]     = make_float4(z[0], z[1], z[2], z[3]);
            *(float4*)&g_XW[(size_t)gr * 128 + tcol * 8 + 4] = make_float4(z[4], z[5], z[6], z[7]);
        }
    }
}

// ---------------- graph machinery ----------------
__device__ __forceinline__ int edge_at(const void* edge, int e, int which_row, int i) {
    if (g_is64) {
        const long long* p = (const long long*)edge;
        return (int)p[(size_t)which_row * e + i];
    } else {
        const int* p = (const int*)edge;
        return p[(size_t)which_row * e + i];
    }
}

__global__ void deg_kernel(const void* __restrict__ edge, int e) {
    for (int i = blockIdx.x * blockDim.x + threadIdx.x; i < e; i += gridDim.x * blockDim.x) {
        int d = edge_at(edge, e, 1, i);
        atomicAdd(&g_deg[d], 1);
    }
}

__global__ void dinv_kernel(int n) {
    int i = blockIdx.x * blockDim.x + threadIdx.x;
    if (i < n) g_dinv[i] = rsqrtf((float)(g_deg[i] + 1));
}

__global__ void scan_kernel(int n) {
    __shared__ int sh[1024];
    __shared__ int carry_s;
    int tx = threadIdx.x;
    if (tx == 0) { carry_s = 0; g_rowoff[0] = 0; }
    __syncthreads();
    for (int base = 0; base < n; base += 1024) {
        int i = base + tx;
        int v = (i < n) ? g_deg[i] : 0;
        sh[tx] = v;
        __syncthreads();
        for (int off = 1; off < 1024; off <<= 1) {
            int t = (tx >= off) ? sh[tx - off] : 0;
            __syncthreads();
            sh[tx] += t;
            __syncthreads();
        }
        int carry = carry_s;
        if (i < n) {
            g_rowoff[i + 1] = sh[tx] + carry;
            g_cursor[i] = sh[tx] - v + carry;
        }
        __syncthreads();
        if (tx == 0) carry_s = carry + sh[1023];
        __syncthreads();
    }
}

__global__ void fill_kernel(const void* __restrict__ edge, int e) {
    for (int i = blockIdx.x * blockDim.x + threadIdx.x; i < e; i += gridDim.x * blockDim.x) {
        int d = edge_at(edge, e, 1, i);
        int s = edge_at(edge, e, 0, i);
        int p = atomicAdd(&g_cursor[d], 1);
        g_csr[p] = s;
    }
}

// ---------------- gather + tanh + classifier + log_softmax ----------------
__global__ void gather_kernel(const float* __restrict__ convb, const float* __restrict__ clsW,
                              const float* __restrict__ clsb, float* __restrict__ out, int n) {
    int gw = (blockIdx.x * blockDim.x + threadIdx.x) >> 5;
    int lane = threadIdx.x & 31;
    if (gw >= n) return;
    const float di = g_dinv[gw];
    const float4* xw4 = (const float4*)g_XW;

    float4 a = xw4[(size_t)gw * 32 + lane];
    float ax = a.x * di, ay = a.y * di, az = a.z * di, aw = a.w * di;

    int beg = g_rowoff[gw], end = g_rowoff[gw + 1];
    for (int j = beg; j < end; j++) {
        int s = g_csr[j];
        float w = g_dinv[s];
        float4 v = xw4[(size_t)s * 32 + lane];
        ax += v.x * w; ay += v.y * w; az += v.z * w; aw += v.w * w;
    }
    float4 cb = ((const float4*)convb)[lane];
    float h0 = tanhf(ax * di + cb.x);
    float h1 = tanhf(ay * di + cb.y);
    float h2 = tanhf(az * di + cb.z);
    float h3 = tanhf(aw * di + cb.w);

    int c0 = lane * 4;
    float lo[OUTC];
#pragma unroll
    for (int o = 0; o < OUTC; o++) {
        lo[o] = h0 * clsW[(size_t)c0 * OUTC + o]
              + h1 * clsW[(size_t)(c0 + 1) * OUTC + o]
              + h2 * clsW[(size_t)(c0 + 2) * OUTC + o]
              + h3 * clsW[(size_t)(c0 + 3) * OUTC + o];
    }
#pragma unroll
    for (int off = 16; off; off >>= 1)
#pragma unroll
        for (int o = 0; o < OUTC; o++)
            lo[o] += __shfl_xor_sync(0xffffffffu, lo[o], off);

    if (lane == 0) {
        float m = -1e30f;
#pragma unroll
        for (int o = 0; o < OUTC; o++) { lo[o] += clsb[o]; m = fmaxf(m, lo[o]); }
        float s = 0.f;
#pragma unroll
        for (int o = 0; o < OUTC; o++) s += expf(lo[o] - m);
        float lse = m + logf(s);
#pragma unroll
        for (int o = 0; o < OUTC; o++) out[(size_t)gw * OUTC + o] = lo[o] - lse;
    }
}

// ---------------- launch ----------------
extern "C" void kernel_launch(void* const* d_in, const int* in_sizes, int n_in,
                              void* d_out, int out_size) {
    const float* low_x      = (const float*)d_in[1];
    const float* cov_x      = (const float*)d_in[2];
    const void*  edge       = d_in[3];
    const float* bn_low_g   = (const float*)d_in[4];
    const float* bn_low_b   = (const float*)d_in[5];
    const float* bn_high_g  = (const float*)d_in[6];
    const float* bn_high_b  = (const float*)d_in[7];
    const float* lin_low_W  = (const float*)d_in[8];
    const float* lin_low_b  = (const float*)d_in[9];
    const float* mlp_low_g  = (const float*)d_in[10];
    const float* mlp_low_b  = (const float*)d_in[11];
    const float* lin_high_W = (const float*)d_in[12];
    const float* lin_high_b = (const float*)d_in[13];
    const float* mlp_high_g = (const float*)d_in[14];
    const float* mlp_high_b = (const float*)d_in[15];
    const float* conv1_W    = (const float*)d_in[16];
    const float* conv1_b    = (const float*)d_in[17];
    const float* cls_W      = (const float*)d_in[18];
    const float* cls_b      = (const float*)d_in[19];

    int n = in_sizes[1] / LOWD;
    int e = in_sizes[3] / 2;
    float invn = 1.f / (float)n;
    int nblk = (n + 127) / 128;

    zero_kernel<<<(n + 255) / 256, 256>>>(n);
    detect_kernel<<<1, 256>>>((const int*)edge, e);

    // pass 1: input BN stats (coalesced)
    colstats2_kernel<<<dim3(HIGHD / 64, 64), 256>>>(cov_x, n, HIGHD, 0);
    colstats2_kernel<<<dim3(1, 512), 256>>>(low_x, n, LOWD, 1);
    finalize_kernel<<<HIGHD / 256, 256>>>(bn_high_g, bn_high_b, HIGHD, invn, 0);
    finalize_kernel<<<1, LOWD>>>(bn_low_g, bn_low_b, LOWD, invn, 1);

    // fold BN1 into linears
    foldWt_kernel<<<(HIGHD * EMB) / 256, 256>>>(lin_high_W);
    foldbias_kernel<<<EMB, 256>>>(lin_high_W, lin_high_b, HIGHD, 0);
    foldW_kernel<<<(LOWD * EMB) / 256, 256>>>(lin_low_W, LOWD * EMB, 1);
    foldbias_kernel<<<EMB, 256>>>(lin_low_W, lin_low_b, LOWD, 1);

    // pass 2: GEMMs + relu + post-relu stats
    gemm_mma_kernel<<<nblk, 256>>>(cov_x, n);
    gemm_relu_stats_kernel<<<nblk, 256>>>(low_x, n);

    // fold BN2 into conv1_W
    finalize_kernel<<<1, EMB>>>(mlp_high_g, mlp_high_b, EMB, invn, 2);
    finalize_kernel<<<1, EMB>>>(mlp_low_g, mlp_low_b, EMB, invn, 3);
    foldW_kernel<<<(2 * EMB * HID) / 256, 256>>>(conv1_W, 2 * EMB * HID, 2);
    foldbias_kernel<<<HID, 256>>>(conv1_W, (const float*)0, 2 * EMB, 2);

    // xw = combined @ conv1_W
    gemm2_kernel<<<nblk, 256>>>(n);

    // graph: degree -> dinv -> CSR
    deg_kernel<<<2048, 256>>>(edge, e);
    dinv_kernel<<<(n + 255) / 256, 256>>>(n);
    scan_kernel<<<1, 1024>>>(n);
    fill_kernel<<<2048, 256>>>(edge, e);

    // aggregate + tanh + classifier + log_softmax
    gather_kernel<<<(n * 32 + 255) / 256, 256>>>(conv1_b, cls_W, cls_b, (float*)d_out, n);
}

// round 6
// speedup vs baseline: 3.6424x; 2.0775x over previous
#include <cuda_runtime.h>
#include <cuda_fp16.h>
#include <math.h>
#include <stdint.h>

#define NN    50000
#define EE    1600000
#define HIGHD 4096
#define LOWD  64
#define EMB   128
#define HID   128
#define OUTC  10
#define BNEPS 1e-5f
#define KCH   32
#define NCHUNK (HIGHD / KCH)        // 128
#define NBLK  ((NN + 127) / 128)    // 391
#define SC1   64.0f
#define SC1I  (1.0f / 64.0f)
#define SC2   32.0f
#define SC2I  (1.0f / 32.0f)

// ---------------- scratch (static device memory; no allocations) ----------------
__device__ __half g_Bh[(size_t)HIGHD * EMB];            // W1h^T fp16 (x SC1), pre-swizzled per 32-K chunk
__device__ __half g_Wc2h[(size_t)2 * EMB * HID];        // conv1 W' fp16 (x SC2), pre-swizzled, 8 chunks
__device__ __half g_Zth[(size_t)NBLK * 4 * 128 * 32];   // high Z, tiled+swizzled fp16
__device__ __half g_Ztl[(size_t)NBLK * 4 * 128 * 32];   // low Z, tiled+swizzled fp16
__device__ __half g_XWh[(size_t)NN * HID];              // xw fp16 row-major
__device__ float g_c1h[EMB];
__device__ float g_W1l[LOWD * EMB];
__device__ float g_c1l[EMB];
__device__ float g_crow[HID];
__device__ float g_sum_h[HIGHD], g_ssq_h[HIGHD];
__device__ float g_sum_l[LOWD],  g_ssq_l[LOWD];
__device__ float g_scale_h[HIGHD], g_shift_h[HIGHD];
__device__ float g_scale_l[LOWD],  g_shift_l[LOWD];
__device__ float g_sum2[2 * EMB], g_ssq2[2 * EMB];
__device__ float g_scale2[2 * EMB], g_shift2[2 * EMB];
__device__ int   g_deg[NN];
__device__ float g_dinv[NN];
__device__ int   g_rowoff[NN + 1];
__device__ int   g_cursor[NN];
__device__ int   g_csr[EE];
__device__ int   g_is64;

// ---------------- PTX helpers (portable: ldmatrix sm_75+, mma.sync fp16 sm_80+) ----------------
__device__ __forceinline__ uint32_t smem_u32(const void* p) {
    uint32_t a;
    asm("{ .reg .u64 t; cvta.to.shared.u64 t, %1; cvt.u32.u64 %0, t; }" : "=r"(a) : "l"(p));
    return a;
}
#define LDMX4(r, a) \
    asm volatile("ldmatrix.sync.aligned.m8n8.x4.shared.b16 {%0,%1,%2,%3}, [%4];" \
        : "=r"((r)[0]), "=r"((r)[1]), "=r"((r)[2]), "=r"((r)[3]) : "r"(a))

__device__ __forceinline__ void mma_f16(float* c, const uint32_t* a, uint32_t b0, uint32_t b1) {
    asm volatile(
        "mma.sync.aligned.m16n8k16.row.col.f32.f16.f16.f32 "
        "{%0,%1,%2,%3}, {%4,%5,%6,%7}, {%8,%9}, {%0,%1,%2,%3};"
        : "+f"(c[0]), "+f"(c[1]), "+f"(c[2]), "+f"(c[3])
        : "r"(a[0]), "r"(a[1]), "r"(a[2]), "r"(a[3]), "r"(b0), "r"(b1));
}
__device__ __forceinline__ uint32_t h2u(__half2 h) { return *reinterpret_cast<uint32_t*>(&h); }

// ---------------- small utility kernels ----------------
__global__ void zero_kernel(int n) {
    int i = blockIdx.x * blockDim.x + threadIdx.x;
    if (i < HIGHD) { g_sum_h[i] = 0.f; g_ssq_h[i] = 0.f; }
    if (i < LOWD)  { g_sum_l[i] = 0.f; g_ssq_l[i] = 0.f; }
    if (i < 2 * EMB) { g_sum2[i] = 0.f; g_ssq2[i] = 0.f; }
    if (i < n) g_deg[i] = 0;
}

__global__ void detect_kernel(const int* __restrict__ edge_words, int e) {
    __shared__ int flag;
    if (threadIdx.x == 0) flag = 0;
    __syncthreads();
    int m = e < 1024 ? e : 1024;
    for (int i = threadIdx.x; i < m; i += blockDim.x)
        if (edge_words[2 * i + 1] != 0) flag = 1;
    __syncthreads();
    if (threadIdx.x == 0) g_is64 = (flag ? 0 : 1);
}

// high-dim column stats, float4 vectorized; block covers 1024 cols, rows grid-strided
__global__ void colstats4_kernel(const float* __restrict__ x, int n) {
    int c4 = blockIdx.x * 1024 + threadIdx.x * 4;
    float s0 = 0, s1 = 0, s2 = 0, s3 = 0, q0 = 0, q1 = 0, q2 = 0, q3 = 0;
    for (int r = blockIdx.y; r < n; r += gridDim.y) {
        float4 v = *(const float4*)&x[(size_t)r * HIGHD + c4];
        s0 += v.x; q0 += v.x * v.x;
        s1 += v.y; q1 += v.y * v.y;
        s2 += v.z; q2 += v.z * v.z;
        s3 += v.w; q3 += v.w * v.w;
    }
    atomicAdd(&g_sum_h[c4 + 0], s0); atomicAdd(&g_ssq_h[c4 + 0], q0);
    atomicAdd(&g_sum_h[c4 + 1], s1); atomicAdd(&g_ssq_h[c4 + 1], q1);
    atomicAdd(&g_sum_h[c4 + 2], s2); atomicAdd(&g_ssq_h[c4 + 2], q2);
    atomicAdd(&g_sum_h[c4 + 3], s3); atomicAdd(&g_ssq_h[c4 + 3], q3);
}

// low-dim column stats: 16 rows x 16 col-groups per block iteration (4KB contiguous)
__global__ void colstats_low_kernel(const float* __restrict__ x, int n) {
    int t = threadIdx.x;
    int cg = t & 15, ro = t >> 4;
    int c4 = cg * 4;
    float s[4] = {0, 0, 0, 0}, q[4] = {0, 0, 0, 0};
    for (int r = blockIdx.x * 16 + ro; r < n; r += gridDim.x * 16) {
        float4 v = *(const float4*)&x[(size_t)r * LOWD + c4];
        s[0] += v.x; q[0] += v.x * v.x;
        s[1] += v.y; q[1] += v.y * v.y;
        s[2] += v.z; q[2] += v.z * v.z;
        s[3] += v.w; q[3] += v.w * v.w;
    }
    __shared__ float sh[2][64];
    if (t < 64) { sh[0][t] = 0.f; sh[1][t] = 0.f; }
    __syncthreads();
#pragma unroll
    for (int k = 0; k < 4; k++) {
        atomicAdd(&sh[0][c4 + k], s[k]);
        atomicAdd(&sh[1][c4 + k], q[k]);
    }
    __syncthreads();
    if (t < 64) { atomicAdd(&g_sum_l[t], sh[0][t]); atomicAdd(&g_ssq_l[t], sh[1][t]); }
}

__global__ void finalize_kernel(const float* __restrict__ g, const float* __restrict__ b,
                                int C, float invn, int which) {
    const float *sum, *ssq; float *scale, *shift;
    if      (which == 0) { sum = g_sum_h;      ssq = g_ssq_h;      scale = g_scale_h;      shift = g_shift_h; }
    else if (which == 1) { sum = g_sum_l;      ssq = g_ssq_l;      scale = g_scale_l;      shift = g_shift_l; }
    else if (which == 2) { sum = g_sum2;       ssq = g_ssq2;       scale = g_scale2;       shift = g_shift2; }
    else                 { sum = g_sum2 + EMB; ssq = g_ssq2 + EMB; scale = g_scale2 + EMB; shift = g_shift2 + EMB; }
    int i = blockIdx.x * blockDim.x + threadIdx.x;
    if (i >= C) return;
    float m = sum[i] * invn;
    float var = ssq[i] * invn - m * m;
    float s = rsqrtf(var + BNEPS) * g[i];
    scale[i] = s;
    shift[i] = b[i] - m * s;
}

// low weight fold (f32, SIMT gemm)
__global__ void foldWl_kernel(const float* __restrict__ W) {
    int i = blockIdx.x * blockDim.x + threadIdx.x;
    if (i < LOWD * EMB) g_W1l[i] = W[i] * g_scale_l[i >> 7];
}

// high weight fold: transpose to [n][k] fp16 (x SC1), per-32k chunk, swizzled
__global__ void foldWt_kernel(const float* __restrict__ W) {
    int i = blockIdx.x * blockDim.x + threadIdx.x;
    if (i >= HIGHD * EMB) return;
    int k = i >> 7, nn = i & 127;
    float v = W[i] * g_scale_h[k] * SC1;
    int c = k >> 5, kk = k & 31;
    uint32_t kb = (uint32_t)kk * 2;
    uint32_t sw = ((kb & 0x30u) ^ (((uint32_t)(nn >> 1) & 3u) << 4)) | (kb & 15u);
    g_Bh[(size_t)c * 4096 + (((uint32_t)nn * 64 + sw) >> 1)] = __float2half(v);
}

// conv weight fold: transpose fp16 (x scale2 x SC2), 8 chunks, swizzled
__global__ void foldWc_kernel(const float* __restrict__ W) {
    int i = blockIdx.x * blockDim.x + threadIdx.x;
    if (i >= 2 * EMB * HID) return;
    int k = i >> 7, nn = i & 127;
    float v = W[i] * g_scale2[k] * SC2;
    int c = k >> 5, kk = k & 31;
    uint32_t kb = (uint32_t)kk * 2;
    uint32_t sw = ((kb & 0x30u) ^ (((uint32_t)(nn >> 1) & 3u) << 4)) | (kb & 15u);
    g_Wc2h[(size_t)c * 4096 + (((uint32_t)nn * 64 + sw) >> 1)] = __float2half(v);
}

__global__ void foldbias_kernel(const float* __restrict__ W, const float* __restrict__ linb,
                                int K, int which) {
    const float* shift = (which == 0) ? g_shift_h : (which == 1) ? g_shift_l : g_shift2;
    float* c1          = (which == 0) ? g_c1h     : (which == 1) ? g_c1l     : g_crow;
    __shared__ float red[256];
    int k = blockIdx.x;
    float s = 0.f;
    for (int j = threadIdx.x; j < K; j += 256) s += shift[j] * W[(size_t)j * 128 + k];
    red[threadIdx.x] = s;
    __syncthreads();
    for (int off = 128; off; off >>= 1) {
        if ((int)threadIdx.x < off) red[threadIdx.x] += red[threadIdx.x + off];
        __syncthreads();
    }
    if (threadIdx.x == 0) c1[k] = (linb ? linb[k] : 0.f) + red[0];
}

// ---------------- GEMM 1 (high): pure fp16 mma, Z -> tiled fp16 + BN2 stats ----------------
__global__ void __launch_bounds__(256, 2) gemm_mma_kernel(const float* __restrict__ A, int n) {
    __shared__ __align__(16) __half sAh[128 * 32];
    __shared__ __align__(16) __half sBh[128 * 32];
    __shared__ float ssum[128], ssqs[128];

    const int tid = threadIdx.x;
    const int wid = tid >> 5, lane = tid & 31;
    const int wm = wid & 3;
    const int wn = wid >> 2;
    const int row0 = blockIdx.x * 128;

    if (tid < 128) { ssum[tid] = 0.f; ssqs[tid] = 0.f; }

    // producer: warp w covers rows w*16..w*16+15; per i, 4 full rows, contiguous 512B per LDG
    int prow[4];
    const float* aptr[4];
    bool avalid[4];
    uint32_t sdst[4];
#pragma unroll
    for (int i = 0; i < 4; i++) {
        prow[i] = wid * 16 + i * 4 + (lane >> 3);
        avalid[i] = (row0 + prow[i]) < n;
        aptr[i] = A + (size_t)(row0 + prow[i]) * HIGHD + (lane & 7) * 4;
        sdst[i] = (uint32_t)prow[i] * 64 +
                  (((uint32_t)(lane & 7) * 8) ^ ((((uint32_t)prow[i] >> 1) & 3u) << 4));
    }
    const uint4* Bh4 = (const uint4*)g_Bh;

    const uint32_t aB = smem_u32(sAh);
    const uint32_t bB = smem_u32(sBh);
    const int lrA = lane & 15;
    const uint32_t lkA = ((uint32_t)(lane >> 4)) << 4;
    const uint32_t swA = (((uint32_t)(lrA >> 1) & 3u) << 4);
    const int lrB = (lane & 7) + ((lane >> 4) << 3);
    const uint32_t lkB = ((uint32_t)(lane & 8)) << 1;
    const uint32_t swB = (((uint32_t)(lrB >> 1) & 3u) << 4);

    float acc[2][8][4];
#pragma unroll
    for (int mt = 0; mt < 2; mt++)
#pragma unroll
        for (int j = 0; j < 8; j++)
#pragma unroll
            for (int q = 0; q < 4; q++) acc[mt][j][q] = 0.f;

    float4 ar[4];
    uint4 bh[2];
#pragma unroll
    for (int i = 0; i < 4; i++)
        ar[i] = avalid[i] ? *(const float4*)aptr[i] : make_float4(0.f, 0.f, 0.f, 0.f);
#pragma unroll
    for (int j = 0; j < 2; j++) bh[j] = Bh4[tid + j * 256];

    for (int c = 0; c < NCHUNK; c++) {
        __syncthreads();
#pragma unroll
        for (int i = 0; i < 4; i++) {
            __half2 h01 = __floats2half2_rn(ar[i].x, ar[i].y);
            __half2 h23 = __floats2half2_rn(ar[i].z, ar[i].w);
            *(uint2*)((char*)sAh + sdst[i]) = make_uint2(h2u(h01), h2u(h23));
        }
#pragma unroll
        for (int j = 0; j < 2; j++) ((uint4*)sBh)[tid + j * 256] = bh[j];
        __syncthreads();

        if (c + 1 < NCHUNK) {
#pragma unroll
            for (int i = 0; i < 4; i++)
                ar[i] = avalid[i] ? *(const float4*)(aptr[i] + (c + 1) * KCH)
                                  : make_float4(0.f, 0.f, 0.f, 0.f);
#pragma unroll
            for (int j = 0; j < 2; j++)
                bh[j] = Bh4[(size_t)(c + 1) * 512 + tid + j * 256];
        }

#pragma unroll
        for (int ks = 0; ks < 2; ks++) {
            uint32_t af[2][4];
#pragma unroll
            for (int mt = 0; mt < 2; mt++) {
                uint32_t off = (uint32_t)(wm * 32 + mt * 16 + lrA) * 64 +
                               (((uint32_t)(ks * 32) + lkA) ^ swA);
                LDMX4(af[mt], aB + off);
            }
#pragma unroll
            for (int g4 = 0; g4 < 4; g4++) {
                uint32_t boff = (uint32_t)(wn * 64 + g4 * 16 + lrB) * 64 +
                                (((uint32_t)(ks * 32) + lkB) ^ swB);
                uint32_t bf[4];
                LDMX4(bf, bB + boff);
#pragma unroll
                for (int mt = 0; mt < 2; mt++) {
                    mma_f16(acc[mt][g4 * 2 + 0], af[mt], bf[0], bf[1]);
                    mma_f16(acc[mt][g4 * 2 + 1], af[mt], bf[2], bf[3]);
                }
            }
        }
    }

    // epilogue: unscale + bias + relu, store tiled fp16 Z, BN2 stats
    const int g = lane >> 2, t4 = lane & 3;
    __half* zt = g_Zth + (size_t)blockIdx.x * 16384;
#pragma unroll
    for (int j = 0; j < 8; j++) {
        int col = wn * 64 + j * 8 + t4 * 2;
        int chunk = col >> 5;
        uint32_t kb = (uint32_t)(col & 31) * 2;
        float c1a = g_c1h[col], c1b = g_c1h[col + 1];
        float sa = 0.f, sb = 0.f, qa = 0.f, qb = 0.f;
#pragma unroll
        for (int mt = 0; mt < 2; mt++) {
#pragma unroll
            for (int h = 0; h < 2; h++) {
                int rloc = wm * 32 + mt * 16 + g + h * 8;
                float x0 = fmaxf(acc[mt][j][h * 2 + 0] * SC1I + c1a, 0.f);
                float x1 = fmaxf(acc[mt][j][h * 2 + 1] * SC1I + c1b, 0.f);
                uint32_t bo = (uint32_t)chunk * 8192 + (uint32_t)rloc * 64 +
                              (kb ^ ((((uint32_t)rloc >> 1) & 3u) << 4));
                *(__half2*)((char*)zt + bo) = __floats2half2_rn(x0, x1);
                if (row0 + rloc < n) { sa += x0; sb += x1; qa += x0 * x0; qb += x1 * x1; }
            }
        }
        atomicAdd(&ssum[col], sa); atomicAdd(&ssum[col + 1], sb);
        atomicAdd(&ssqs[col], qa); atomicAdd(&ssqs[col + 1], qb);
    }
    __syncthreads();
    if (tid < 128) {
        atomicAdd(&g_sum2[tid], ssum[tid]);
        atomicAdd(&g_ssq2[tid], ssqs[tid]);
    }
}

// ---------------- GEMM low (K=64, f32 SIMT): Z -> tiled fp16 + stats ----------------
__global__ __launch_bounds__(256) void gemm_relu_stats_kernel(const float* __restrict__ A, int n) {
    __shared__ float As[16][128];
    __shared__ float Bs[16][128];
    const int tx = threadIdx.x;
    const int trow = tx >> 4, tcol = tx & 15;
    const int row0 = blockIdx.x * 128;

    float acc[8][8];
#pragma unroll
    for (int i = 0; i < 8; i++)
#pragma unroll
        for (int j = 0; j < 8; j++) acc[i][j] = 0.f;

    for (int k0 = 0; k0 < LOWD; k0 += 16) {
#pragma unroll
        for (int i = 0; i < 2; i++) {
            int f = tx + i * 256;
            int r = f >> 2;
            int kc = (f & 3) << 2;
            int gr = row0 + r;
            float4 v = make_float4(0.f, 0.f, 0.f, 0.f);
            if (gr < n) v = *(const float4*)&A[(size_t)gr * LOWD + k0 + kc];
            As[kc + 0][r] = v.x; As[kc + 1][r] = v.y; As[kc + 2][r] = v.z; As[kc + 3][r] = v.w;
        }
#pragma unroll
        for (int i = 0; i < 2; i++) {
            int f = tx + i * 256;
            int r = f >> 5;
            int cc = (f & 31) << 2;
            *(float4*)&Bs[r][cc] = *(const float4*)&g_W1l[(size_t)(k0 + r) * 128 + cc];
        }
        __syncthreads();
#pragma unroll
        for (int k = 0; k < 16; k++) {
            float a[8], b[8];
            *(float4*)&a[0] = *(const float4*)&As[k][trow * 8];
            *(float4*)&a[4] = *(const float4*)&As[k][trow * 8 + 4];
            *(float4*)&b[0] = *(const float4*)&Bs[k][tcol * 8];
            *(float4*)&b[4] = *(const float4*)&Bs[k][tcol * 8 + 4];
#pragma unroll
            for (int i = 0; i < 8; i++)
#pragma unroll
                for (int j = 0; j < 8; j++) acc[i][j] += a[i] * b[j];
        }
        __syncthreads();
    }

    float cs[8], cq[8], c1v[8];
#pragma unroll
    for (int j = 0; j < 8; j++) { cs[j] = 0.f; cq[j] = 0.f; c1v[j] = g_c1l[tcol * 8 + j]; }

    __half* zt = g_Ztl + (size_t)blockIdx.x * 16384;
    const int chunk = tcol >> 2;
    const uint32_t unit = (uint32_t)(tcol & 3) * 16;
#pragma unroll
    for (int i = 0; i < 8; i++) {
        int rloc = trow * 8 + i;
        int gr = row0 + rloc;
        float z[8];
#pragma unroll
        for (int j = 0; j < 8; j++) {
            float v = acc[i][j] + c1v[j];
            z[j] = v > 0.f ? v : 0.f;
        }
        if (gr < n) {
#pragma unroll
            for (int j = 0; j < 8; j++) { cs[j] += z[j]; cq[j] += z[j] * z[j]; }
        }
        __half2 p0 = __floats2half2_rn(z[0], z[1]);
        __half2 p1 = __floats2half2_rn(z[2], z[3]);
        __half2 p2 = __floats2half2_rn(z[4], z[5]);
        __half2 p3 = __floats2half2_rn(z[6], z[7]);
        uint32_t bo = (uint32_t)chunk * 8192 + (uint32_t)rloc * 64 +
                      (unit ^ ((((uint32_t)rloc >> 1) & 3u) << 4));
        *(uint4*)((char*)zt + bo) = make_uint4(h2u(p0), h2u(p1), h2u(p2), h2u(p3));
    }
    __syncthreads();
#pragma unroll
    for (int j = 0; j < 8; j++) As[trow][tcol * 8 + j] = cs[j];
    __syncthreads();
    if (tx < 128) {
        float s = 0.f;
#pragma unroll
        for (int r = 0; r < 16; r++) s += As[r][tx];
        atomicAdd(&g_sum2[EMB + tx], s);
    }
    __syncthreads();
#pragma unroll
    for (int j = 0; j < 8; j++) As[trow][tcol * 8 + j] = cq[j];
    __syncthreads();
    if (tx < 128) {
        float s = 0.f;
#pragma unroll
        for (int r = 0; r < 16; r++) s += As[r][tx];
        atomicAdd(&g_ssq2[EMB + tx], s);
    }
}

// ---------------- GEMM 2: XW = [Zh|Zl] @ Wc + crow, fp16 mma, fp16 out ----------------
__global__ void __launch_bounds__(256, 2) gemm2_kernel(int n) {
    __shared__ __align__(16) __half sAh[128 * 32];
    __shared__ __align__(16) __half sBh[128 * 32];

    const int tid = threadIdx.x;
    const int wid = tid >> 5, lane = tid & 31;
    const int wm = wid & 3, wn = wid >> 2;
    const int row0 = blockIdx.x * 128;

    const uint4* At = (const uint4*)(g_Zth + (size_t)blockIdx.x * 16384);
    const uint4* Al = (const uint4*)(g_Ztl + (size_t)blockIdx.x * 16384);
    const uint4* Bt = (const uint4*)g_Wc2h;

    const uint32_t aB = smem_u32(sAh);
    const uint32_t bB = smem_u32(sBh);
    const int lrA = lane & 15;
    const uint32_t lkA = ((uint32_t)(lane >> 4)) << 4;
    const uint32_t swA = (((uint32_t)(lrA >> 1) & 3u) << 4);
    const int lrB = (lane & 7) + ((lane >> 4) << 3);
    const uint32_t lkB = ((uint32_t)(lane & 8)) << 1;
    const uint32_t swB = (((uint32_t)(lrB >> 1) & 3u) << 4);

    float acc[2][8][4];
#pragma unroll
    for (int mt = 0; mt < 2; mt++)
#pragma unroll
        for (int j = 0; j < 8; j++)
#pragma unroll
            for (int q = 0; q < 4; q++) acc[mt][j][q] = 0.f;

    uint4 a4[2], b4[2];
    a4[0] = At[tid]; a4[1] = At[tid + 256];
    b4[0] = Bt[tid]; b4[1] = Bt[tid + 256];

    for (int c = 0; c < 8; c++) {
        __syncthreads();
        ((uint4*)sAh)[tid] = a4[0]; ((uint4*)sAh)[tid + 256] = a4[1];
        ((uint4*)sBh)[tid] = b4[0]; ((uint4*)sBh)[tid + 256] = b4[1];
        __syncthreads();
        if (c + 1 < 8) {
            const uint4* src = (c + 1 < 4) ? (At + (size_t)(c + 1) * 512) : (Al + (size_t)(c - 3) * 512);
            a4[0] = src[tid]; a4[1] = src[tid + 256];
            b4[0] = Bt[(size_t)(c + 1) * 512 + tid]; b4[1] = Bt[(size_t)(c + 1) * 512 + tid + 256];
        }
#pragma unroll
        for (int ks = 0; ks < 2; ks++) {
            uint32_t af[2][4];
#pragma unroll
            for (int mt = 0; mt < 2; mt++) {
                uint32_t off = (uint32_t)(wm * 32 + mt * 16 + lrA) * 64 +
                               (((uint32_t)(ks * 32) + lkA) ^ swA);
                LDMX4(af[mt], aB + off);
            }
#pragma unroll
            for (int g4 = 0; g4 < 4; g4++) {
                uint32_t boff = (uint32_t)(wn * 64 + g4 * 16 + lrB) * 64 +
                                (((uint32_t)(ks * 32) + lkB) ^ swB);
                uint32_t bf[4];
                LDMX4(bf, bB + boff);
#pragma unroll
                for (int mt = 0; mt < 2; mt++) {
                    mma_f16(acc[mt][g4 * 2 + 0], af[mt], bf[0], bf[1]);
                    mma_f16(acc[mt][g4 * 2 + 1], af[mt], bf[2], bf[3]);
                }
            }
        }
    }

    const int g = lane >> 2, t4 = lane & 3;
#pragma unroll
    for (int j = 0; j < 8; j++) {
        int col = wn * 64 + j * 8 + t4 * 2;
        float ca = g_crow[col], cb = g_crow[col + 1];
#pragma unroll
        for (int mt = 0; mt < 2; mt++)
#pragma unroll
            for (int h = 0; h < 2; h++) {
                int r = row0 + wm * 32 + mt * 16 + g + h * 8;
                if (r < n) {
                    float x0 = acc[mt][j][h * 2 + 0] * SC2I + ca;
                    float x1 = acc[mt][j][h * 2 + 1] * SC2I + cb;
                    *(__half2*)&g_XWh[(size_t)r * 128 + col] = __floats2half2_rn(x0, x1);
                }
            }
    }
}

// ---------------- graph machinery ----------------
__device__ __forceinline__ int edge_at(const void* edge, int e, int which_row, int i) {
    if (g_is64) {
        const long long* p = (const long long*)edge;
        return (int)p[(size_t)which_row * e + i];
    } else {
        const int* p = (const int*)edge;
        return p[(size_t)which_row * e + i];
    }
}

__global__ void deg_kernel(const void* __restrict__ edge, int e) {
    for (int i = blockIdx.x * blockDim.x + threadIdx.x; i < e; i += gridDim.x * blockDim.x) {
        int d = edge_at(edge, e, 1, i);
        atomicAdd(&g_deg[d], 1);
    }
}

__global__ void dinv_kernel(int n) {
    int i = blockIdx.x * blockDim.x + threadIdx.x;
    if (i < n) g_dinv[i] = rsqrtf((float)(g_deg[i] + 1));
}

// single-block warp-shuffle scan over 1024-wide chunks
__global__ void scan_kernel(int n) {
    __shared__ int wsum[32];
    __shared__ int s_carry;
    int tx = threadIdx.x, lane = tx & 31, wid = tx >> 5;
    if (tx == 0) { s_carry = 0; g_rowoff[0] = 0; }
    __syncthreads();
    for (int base = 0; base < n; base += 1024) {
        int i = base + tx;
        int v = (i < n) ? g_deg[i] : 0;
        int inc = v;
#pragma unroll
        for (int off = 1; off < 32; off <<= 1) {
            int t = __shfl_up_sync(0xffffffffu, inc, off);
            if (lane >= off) inc += t;
        }
        if (lane == 31) wsum[wid] = inc;
        __syncthreads();
        if (wid == 0) {
            int w = wsum[lane];
            int wi = w;
#pragma unroll
            for (int off = 1; off < 32; off <<= 1) {
                int t = __shfl_up_sync(0xffffffffu, wi, off);
                if (lane >= off) wi += t;
            }
            wsum[lane] = wi - w;   // exclusive prefix of warp sums
        }
        __syncthreads();
        int incl = inc + wsum[wid] + s_carry;
        if (i < n) {
            g_rowoff[i + 1] = incl;
            g_cursor[i] = incl - v;
        }
        __syncthreads();
        if (tx == 1023) s_carry = incl;
        __syncthreads();
    }
}

__global__ void fill_kernel(const void* __restrict__ edge, int e) {
    for (int i = blockIdx.x * blockDim.x + threadIdx.x; i < e; i += gridDim.x * blockDim.x) {
        int d = edge_at(edge, e, 1, i);
        int s = edge_at(edge, e, 0, i);
        int p = atomicAdd(&g_cursor[d], 1);
        g_csr[p] = s;
    }
}

// ---------------- gather (fp16 XW) + tanh + classifier + log_softmax ----------------
__global__ void gather_kernel(const float* __restrict__ convb, const float* __restrict__ clsW,
                              const float* __restrict__ clsb, float* __restrict__ out, int n) {
    int gw = (blockIdx.x * blockDim.x + threadIdx.x) >> 5;
    int lane = threadIdx.x & 31;
    if (gw >= n) return;
    const float di = g_dinv[gw];
    const uint2* xw2 = (const uint2*)g_XWh;

    uint2 u = xw2[(size_t)gw * 32 + lane];
    float2 f0 = __half22float2(*(__half2*)&u.x);
    float2 f1 = __half22float2(*(__half2*)&u.y);
    float ax = f0.x * di, ay = f0.y * di, az = f1.x * di, aw = f1.y * di;

    int beg = g_rowoff[gw], end = g_rowoff[gw + 1];
    for (int j = beg; j < end; j++) {
        int s = g_csr[j];
        float w = g_dinv[s];
        uint2 v = xw2[(size_t)s * 32 + lane];
        float2 v0 = __half22float2(*(__half2*)&v.x);
        float2 v1 = __half22float2(*(__half2*)&v.y);
        ax += v0.x * w; ay += v0.y * w; az += v1.x * w; aw += v1.y * w;
    }
    float4 cb = ((const float4*)convb)[lane];
    float h0 = tanhf(ax * di + cb.x);
    float h1 = tanhf(ay * di + cb.y);
    float h2 = tanhf(az * di + cb.z);
    float h3 = tanhf(aw * di + cb.w);

    int c0 = lane * 4;
    float lo[OUTC];
#pragma unroll
    for (int o = 0; o < OUTC; o++) {
        lo[o] = h0 * clsW[(size_t)c0 * OUTC + o]
              + h1 * clsW[(size_t)(c0 + 1) * OUTC + o]
              + h2 * clsW[(size_t)(c0 + 2) * OUTC + o]
              + h3 * clsW[(size_t)(c0 + 3) * OUTC + o];
    }
#pragma unroll
    for (int off = 16; off; off >>= 1)
#pragma unroll
        for (int o = 0; o < OUTC; o++)
            lo[o] += __shfl_xor_sync(0xffffffffu, lo[o], off);

    if (lane == 0) {
        float m = -1e30f;
#pragma unroll
        for (int o = 0; o < OUTC; o++) { lo[o] += clsb[o]; m = fmaxf(m, lo[o]); }
        float s = 0.f;
#pragma unroll
        for (int o = 0; o < OUTC; o++) s += expf(lo[o] - m);
        float lse = m + logf(s);
#pragma unroll
        for (int o = 0; o < OUTC; o++) out[(size_t)gw * OUTC + o] = lo[o] - lse;
    }
}

// ---------------- launch ----------------
extern "C" void kernel_launch(void* const* d_in, const int* in_sizes, int n_in,
                              void* d_out, int out_size) {
    const float* low_x      = (const float*)d_in[1];
    const float* cov_x      = (const float*)d_in[2];
    const void*  edge       = d_in[3];
    const float* bn_low_g   = (const float*)d_in[4];
    const float* bn_low_b   = (const float*)d_in[5];
    const float* bn_high_g  = (const float*)d_in[6];
    const float* bn_high_b  = (const float*)d_in[7];
    const float* lin_low_W  = (const float*)d_in[8];
    const float* lin_low_b  = (const float*)d_in[9];
    const float* mlp_low_g  = (const float*)d_in[10];
    const float* mlp_low_b  = (const float*)d_in[11];
    const float* lin_high_W = (const float*)d_in[12];
    const float* lin_high_b = (const float*)d_in[13];
    const float* mlp_high_g = (const float*)d_in[14];
    const float* mlp_high_b = (const float*)d_in[15];
    const float* conv1_W    = (const float*)d_in[16];
    const float* conv1_b    = (const float*)d_in[17];
    const float* cls_W      = (const float*)d_in[18];
    const float* cls_b      = (const float*)d_in[19];

    int n = in_sizes[1] / LOWD;
    int e = in_sizes[3] / 2;
    float invn = 1.f / (float)n;
    int nblk = (n + 127) / 128;

    zero_kernel<<<(n + 255) / 256, 256>>>(n);
    detect_kernel<<<1, 256>>>((const int*)edge, e);

    // graph build (independent of feature path)
    deg_kernel<<<2048, 256>>>(edge, e);
    dinv_kernel<<<(n + 255) / 256, 256>>>(n);
    scan_kernel<<<1, 1024>>>(n);
    fill_kernel<<<2048, 256>>>(edge, e);

    // pass 1: input BN stats
    colstats4_kernel<<<dim3(HIGHD / 1024, 256), 256>>>(cov_x, n);
    colstats_low_kernel<<<128, 256>>>(low_x, n);
    finalize_kernel<<<HIGHD / 256, 256>>>(bn_high_g, bn_high_b, HIGHD, invn, 0);
    finalize_kernel<<<1, LOWD>>>(bn_low_g, bn_low_b, LOWD, invn, 1);

    // fold BN1 into linears
    foldWt_kernel<<<(HIGHD * EMB) / 256, 256>>>(lin_high_W);
    foldbias_kernel<<<EMB, 256>>>(lin_high_W, lin_high_b, HIGHD, 0);
    foldWl_kernel<<<(LOWD * EMB) / 256, 256>>>(lin_low_W);
    foldbias_kernel<<<EMB, 256>>>(lin_low_W, lin_low_b, LOWD, 1);

    // pass 2: GEMMs + relu + post-relu stats
    gemm_mma_kernel<<<nblk, 256>>>(cov_x, n);
    gemm_relu_stats_kernel<<<nblk, 256>>>(low_x, n);

    // fold BN2 into conv1_W
    finalize_kernel<<<1, EMB>>>(mlp_high_g, mlp_high_b, EMB, invn, 2);
    finalize_kernel<<<1, EMB>>>(mlp_low_g, mlp_low_b, EMB, invn, 3);
    foldWc_kernel<<<(2 * EMB * HID) / 256, 256>>>(conv1_W);
    foldbias_kernel<<<HID, 256>>>(conv1_W, (const float*)0, 2 * EMB, 2);

    // xw = combined @ conv1_W
    gemm2_kernel<<<nblk, 256>>>(n);

    // aggregate + tanh + classifier + log_softmax
    gather_kernel<<<(n * 32 + 255) / 256, 256>>>(conv1_b, cls_W, cls_b, (float*)d_out, n);
}

// round 8
// speedup vs baseline: 3.7208x; 1.0215x over previous
#include <cuda_runtime.h>
#include <cuda_fp16.h>
#include <math.h>
#include <stdint.h>

#define NN    50000
#define EE    1600000
#define HIGHD 4096
#define LOWD  64
#define EMB   128
#define HID   128
#define OUTC  10
#define BNEPS 1e-5f
#define KCH   32
#define NCHUNK (HIGHD / KCH)        // 128
#define NBLK  ((NN + 127) / 128)    // 391
#define SC1   64.0f
#define SC1I  (1.0f / 64.0f)
#define SC2   32.0f
#define SC2I  (1.0f / 32.0f)

// ---------------- scratch ----------------
__device__ __half g_Bh[(size_t)HIGHD * EMB];
__device__ __half g_Wc2h[(size_t)2 * EMB * HID];
__device__ __half g_Zth[(size_t)NBLK * 4 * 128 * 32];
__device__ __half g_Ztl[(size_t)NBLK * 4 * 128 * 32];
__device__ __half g_XWh[(size_t)NN * HID];
__device__ float g_c1h[EMB];
__device__ float g_W1l[LOWD * EMB];
__device__ float g_c1l[EMB];
__device__ float g_crow[HID];
__device__ float g_sum_h[HIGHD], g_ssq_h[HIGHD];
__device__ float g_sum_l[LOWD],  g_ssq_l[LOWD];
__device__ float g_scale_h[HIGHD], g_shift_h[HIGHD];
__device__ float g_scale_l[LOWD],  g_shift_l[LOWD];
__device__ float g_sum2[2 * EMB], g_ssq2[2 * EMB];
__device__ float g_scale2[2 * EMB], g_shift2[2 * EMB];
__device__ int   g_deg[NN];
__device__ float g_dinv[NN];
__device__ int   g_rowoff[NN + 1];
__device__ int   g_cursor[NN];
__device__ int   g_csr[EE];
__device__ int   g_is64;

// ---------------- PTX helpers ----------------
__device__ __forceinline__ uint32_t smem_u32(const void* p) {
    uint32_t a;
    asm("{ .reg .u64 t; cvta.to.shared.u64 t, %1; cvt.u32.u64 %0, t; }" : "=r"(a) : "l"(p));
    return a;
}
#define LDMX4(r, a) \
    asm volatile("ldmatrix.sync.aligned.m8n8.x4.shared.b16 {%0,%1,%2,%3}, [%4];" \
        : "=r"((r)[0]), "=r"((r)[1]), "=r"((r)[2]), "=r"((r)[3]) : "r"(a))

__device__ __forceinline__ void mma_f16(float* c, const uint32_t* a, uint32_t b0, uint32_t b1) {
    asm volatile(
        "mma.sync.aligned.m16n8k16.row.col.f32.f16.f16.f32 "
        "{%0,%1,%2,%3}, {%4,%5,%6,%7}, {%8,%9}, {%0,%1,%2,%3};"
        : "+f"(c[0]), "+f"(c[1]), "+f"(c[2]), "+f"(c[3])
        : "r"(a[0]), "r"(a[1]), "r"(a[2]), "r"(a[3]), "r"(b0), "r"(b1));
}
__device__ __forceinline__ uint32_t h2u(__half2 h) { return *reinterpret_cast<uint32_t*>(&h); }

// ---------------- 1: zero + edge dtype detect ----------------
__global__ void zero_detect_kernel(int n, const int* __restrict__ edge_words, int e) {
    int i = blockIdx.x * blockDim.x + threadIdx.x;
    if (i < HIGHD) { g_sum_h[i] = 0.f; g_ssq_h[i] = 0.f; }
    if (i < LOWD)  { g_sum_l[i] = 0.f; g_ssq_l[i] = 0.f; }
    if (i < 2 * EMB) { g_sum2[i] = 0.f; g_ssq2[i] = 0.f; }
    if (i < n) g_deg[i] = 0;
    if (blockIdx.x == 0) {
        __shared__ int flag;
        if (threadIdx.x == 0) flag = 0;
        __syncthreads();
        int m = e < 1024 ? e : 1024;
        for (int j = threadIdx.x; j < m; j += blockDim.x)
            if (edge_words[2 * j + 1] != 0) flag = 1;
        __syncthreads();
        if (threadIdx.x == 0) g_is64 = (flag ? 0 : 1);
    }
}

// ---------------- 2: high col stats ----------------
__global__ void colstats4_kernel(const float* __restrict__ x, int n) {
    int c4 = blockIdx.x * 1024 + threadIdx.x * 4;
    float s0 = 0, s1 = 0, s2 = 0, s3 = 0, q0 = 0, q1 = 0, q2 = 0, q3 = 0;
    for (int r = blockIdx.y; r < n; r += gridDim.y) {
        float4 v = *(const float4*)&x[(size_t)r * HIGHD + c4];
        s0 += v.x; q0 += v.x * v.x;
        s1 += v.y; q1 += v.y * v.y;
        s2 += v.z; q2 += v.z * v.z;
        s3 += v.w; q3 += v.w * v.w;
    }
    atomicAdd(&g_sum_h[c4 + 0], s0); atomicAdd(&g_ssq_h[c4 + 0], q0);
    atomicAdd(&g_sum_h[c4 + 1], s1); atomicAdd(&g_ssq_h[c4 + 1], q1);
    atomicAdd(&g_sum_h[c4 + 2], s2); atomicAdd(&g_ssq_h[c4 + 2], q2);
    atomicAdd(&g_sum_h[c4 + 3], s3); atomicAdd(&g_ssq_h[c4 + 3], q3);
}

// ---------------- 3: low col stats ----------------
__global__ void colstats_low_kernel(const float* __restrict__ x, int n) {
    int t = threadIdx.x;
    int cg = t & 15, ro = t >> 4;
    int c4 = cg * 4;
    float s[4] = {0, 0, 0, 0}, q[4] = {0, 0, 0, 0};
    for (int r = blockIdx.x * 16 + ro; r < n; r += gridDim.x * 16) {
        float4 v = *(const float4*)&x[(size_t)r * LOWD + c4];
        s[0] += v.x; q[0] += v.x * v.x;
        s[1] += v.y; q[1] += v.y * v.y;
        s[2] += v.z; q[2] += v.z * v.z;
        s[3] += v.w; q[3] += v.w * v.w;
    }
    __shared__ float sh[2][64];
    if (t < 64) { sh[0][t] = 0.f; sh[1][t] = 0.f; }
    __syncthreads();
#pragma unroll
    for (int k = 0; k < 4; k++) {
        atomicAdd(&sh[0][c4 + k], s[k]);
        atomicAdd(&sh[1][c4 + k], q[k]);
    }
    __syncthreads();
    if (t < 64) { atomicAdd(&g_sum_l[t], sh[0][t]); atomicAdd(&g_ssq_l[t], sh[1][t]); }
}

// ---------------- 4: finalize BN1 (high + low fused) ----------------
__global__ void finalize1_kernel(const float* __restrict__ gh, const float* __restrict__ bh,
                                 const float* __restrict__ gl, const float* __restrict__ bl,
                                 float invn) {
    int i = blockIdx.x * blockDim.x + threadIdx.x;
    if (i < HIGHD) {
        float m = g_sum_h[i] * invn;
        float var = g_ssq_h[i] * invn - m * m;
        float s = rsqrtf(var + BNEPS) * gh[i];
        g_scale_h[i] = s;
        g_shift_h[i] = bh[i] - m * s;
    } else if (i < HIGHD + LOWD) {
        int j = i - HIGHD;
        float m = g_sum_l[j] * invn;
        float var = g_ssq_l[j] * invn - m * m;
        float s = rsqrtf(var + BNEPS) * gl[j];
        g_scale_l[j] = s;
        g_shift_l[j] = bl[j] - m * s;
    }
}

// ---------------- 5: all BN1 folds fused ----------------
// blocks [0,2048): foldWt high; [2048,2080): foldWl; [2080,2208): foldbias high; [2208,2336): foldbias low
__global__ void folds1_kernel(const float* __restrict__ Wh, const float* __restrict__ bh,
                              const float* __restrict__ Wl, const float* __restrict__ bl) {
    __shared__ float red[256];
    int b = blockIdx.x, tx = threadIdx.x;
    if (b < 2048) {
        int i = b * 256 + tx;
        int k = i >> 7, nn = i & 127;
        float v = Wh[i] * g_scale_h[k] * SC1;
        int c = k >> 5, kk = k & 31;
        uint32_t kb = (uint32_t)kk * 2;
        uint32_t sw = ((kb & 0x30u) ^ (((uint32_t)(nn >> 1) & 3u) << 4)) | (kb & 15u);
        g_Bh[(size_t)c * 4096 + (((uint32_t)nn * 64 + sw) >> 1)] = __float2half(v);
    } else if (b < 2080) {
        int i = (b - 2048) * 256 + tx;
        g_W1l[i] = Wl[i] * g_scale_l[i >> 7];
    } else if (b < 2208) {
        int k = b - 2080;
        float s = 0.f;
        for (int j = tx; j < HIGHD; j += 256) s += g_shift_h[j] * Wh[(size_t)j * 128 + k];
        red[tx] = s;
        __syncthreads();
        for (int off = 128; off; off >>= 1) {
            if (tx < off) red[tx] += red[tx + off];
            __syncthreads();
        }
        if (tx == 0) g_c1h[k] = bh[k] + red[0];
    } else {
        int k = b - 2208;
        float s = (tx < LOWD) ? g_shift_l[tx] * Wl[(size_t)tx * 128 + k] : 0.f;
        red[tx] = s;
        __syncthreads();
        for (int off = 128; off; off >>= 1) {
            if (tx < off) red[tx] += red[tx + off];
            __syncthreads();
        }
        if (tx == 0) g_c1l[k] = bl[k] + red[0];
    }
}

// ---------------- 6: GEMM high (fp16 mma, double-buffered) ----------------
__global__ void __launch_bounds__(256, 2) gemm_mma_kernel(const float* __restrict__ A, int n) {
    __shared__ __align__(16) __half sA[2][128 * 32];
    __shared__ __align__(16) __half sB[2][128 * 32];
    __shared__ float ssum[128], ssqs[128];

    const int tid = threadIdx.x;
    const int wid = tid >> 5, lane = tid & 31;
    const int wm = wid & 3;
    const int wn = wid >> 2;
    const int row0 = blockIdx.x * 128;

    if (tid < 128) { ssum[tid] = 0.f; ssqs[tid] = 0.f; }

    int prow[4];
    const float* aptr[4];
    bool avalid[4];
    uint32_t sdst[4];
#pragma unroll
    for (int i = 0; i < 4; i++) {
        prow[i] = wid * 16 + i * 4 + (lane >> 3);
        avalid[i] = (row0 + prow[i]) < n;
        aptr[i] = A + (size_t)(row0 + prow[i]) * HIGHD + (lane & 7) * 4;
        sdst[i] = (uint32_t)prow[i] * 64 +
                  (((uint32_t)(lane & 7) * 8) ^ ((((uint32_t)prow[i] >> 1) & 3u) << 4));
    }
    const uint4* Bh4 = (const uint4*)g_Bh;

    const uint32_t aB0 = smem_u32(sA[0]), aB1 = smem_u32(sA[1]);
    const uint32_t bB0 = smem_u32(sB[0]), bB1 = smem_u32(sB[1]);
    const int lrA = lane & 15;
    const uint32_t lkA = ((uint32_t)(lane >> 4)) << 4;
    const uint32_t swA = (((uint32_t)(lrA >> 1) & 3u) << 4);
    const int lrB = (lane & 7) + ((lane >> 4) << 3);
    const uint32_t lkB = ((uint32_t)(lane & 8)) << 1;
    const uint32_t swB = (((uint32_t)(lrB >> 1) & 3u) << 4);

    float acc[2][8][4];
#pragma unroll
    for (int mt = 0; mt < 2; mt++)
#pragma unroll
        for (int j = 0; j < 8; j++)
#pragma unroll
            for (int q = 0; q < 4; q++) acc[mt][j][q] = 0.f;

    float4 ar[4];
    uint4 bh[2];
#pragma unroll
    for (int i = 0; i < 4; i++)
        ar[i] = avalid[i] ? *(const float4*)aptr[i] : make_float4(0.f, 0.f, 0.f, 0.f);
#pragma unroll
    for (int j = 0; j < 2; j++) bh[j] = Bh4[tid + j * 256];

    // store chunk 0 into buffer 0
#pragma unroll
    for (int i = 0; i < 4; i++) {
        __half2 h01 = __floats2half2_rn(ar[i].x, ar[i].y);
        __half2 h23 = __floats2half2_rn(ar[i].z, ar[i].w);
        *(uint2*)((char*)sA[0] + sdst[i]) = make_uint2(h2u(h01), h2u(h23));
    }
#pragma unroll
    for (int j = 0; j < 2; j++) ((uint4*)sB[0])[tid + j * 256] = bh[j];

    for (int c = 0; c < NCHUNK; c++) {
        __syncthreads();
        if (c + 1 < NCHUNK) {
#pragma unroll
            for (int i = 0; i < 4; i++)
                ar[i] = avalid[i] ? *(const float4*)(aptr[i] + (c + 1) * KCH)
                                  : make_float4(0.f, 0.f, 0.f, 0.f);
#pragma unroll
            for (int j = 0; j < 2; j++)
                bh[j] = Bh4[(size_t)(c + 1) * 512 + tid + j * 256];
        }
        const uint32_t aB = (c & 1) ? aB1 : aB0;
        const uint32_t bB = (c & 1) ? bB1 : bB0;
#pragma unroll
        for (int ks = 0; ks < 2; ks++) {
            uint32_t af[2][4];
#pragma unroll
            for (int mt = 0; mt < 2; mt++) {
                uint32_t off = (uint32_t)(wm * 32 + mt * 16 + lrA) * 64 +
                               (((uint32_t)(ks * 32) + lkA) ^ swA);
                LDMX4(af[mt], aB + off);
            }
#pragma unroll
            for (int g4 = 0; g4 < 4; g4++) {
                uint32_t boff = (uint32_t)(wn * 64 + g4 * 16 + lrB) * 64 +
                                (((uint32_t)(ks * 32) + lkB) ^ swB);
                uint32_t bf[4];
                LDMX4(bf, bB + boff);
#pragma unroll
                for (int mt = 0; mt < 2; mt++) {
                    mma_f16(acc[mt][g4 * 2 + 0], af[mt], bf[0], bf[1]);
                    mma_f16(acc[mt][g4 * 2 + 1], af[mt], bf[2], bf[3]);
                }
            }
        }
        if (c + 1 < NCHUNK) {
            __half* dA = sA[(c + 1) & 1];
            __half* dB = sB[(c + 1) & 1];
#pragma unroll
            for (int i = 0; i < 4; i++) {
                __half2 h01 = __floats2half2_rn(ar[i].x, ar[i].y);
                __half2 h23 = __floats2half2_rn(ar[i].z, ar[i].w);
                *(uint2*)((char*)dA + sdst[i]) = make_uint2(h2u(h01), h2u(h23));
            }
#pragma unroll
            for (int j = 0; j < 2; j++) ((uint4*)dB)[tid + j * 256] = bh[j];
        }
    }

    // epilogue
    const int g = lane >> 2, t4 = lane & 3;
    __half* zt = g_Zth + (size_t)blockIdx.x * 16384;
#pragma unroll
    for (int j = 0; j < 8; j++) {
        int col = wn * 64 + j * 8 + t4 * 2;
        int chunk = col >> 5;
        uint32_t kb = (uint32_t)(col & 31) * 2;
        float c1a = g_c1h[col], c1b = g_c1h[col + 1];
        float sa = 0.f, sb = 0.f, qa = 0.f, qb = 0.f;
#pragma unroll
        for (int mt = 0; mt < 2; mt++) {
#pragma unroll
            for (int h = 0; h < 2; h++) {
                int rloc = wm * 32 + mt * 16 + g + h * 8;
                float x0 = fmaxf(acc[mt][j][h * 2 + 0] * SC1I + c1a, 0.f);
                float x1 = fmaxf(acc[mt][j][h * 2 + 1] * SC1I + c1b, 0.f);
                uint32_t bo = (uint32_t)chunk * 8192 + (uint32_t)rloc * 64 +
                              (kb ^ ((((uint32_t)rloc >> 1) & 3u) << 4));
                *(__half2*)((char*)zt + bo) = __floats2half2_rn(x0, x1);
                if (row0 + rloc < n) { sa += x0; sb += x1; qa += x0 * x0; qb += x1 * x1; }
            }
        }
        atomicAdd(&ssum[col], sa); atomicAdd(&ssum[col + 1], sb);
        atomicAdd(&ssqs[col], qa); atomicAdd(&ssqs[col + 1], qb);
    }
    __syncthreads();
    if (tid < 128) {
        atomicAdd(&g_sum2[tid], ssum[tid]);
        atomicAdd(&g_ssq2[tid], ssqs[tid]);
    }
}

// ---------------- 7: GEMM low (f32 SIMT) ----------------
__global__ __launch_bounds__(256) void gemm_relu_stats_kernel(const float* __restrict__ A, int n) {
    __shared__ float As[16][128];
    __shared__ float Bs[16][128];
    const int tx = threadIdx.x;
    const int trow = tx >> 4, tcol = tx & 15;
    const int row0 = blockIdx.x * 128;

    float acc[8][8];
#pragma unroll
    for (int i = 0; i < 8; i++)
#pragma unroll
        for (int j = 0; j < 8; j++) acc[i][j] = 0.f;

    for (int k0 = 0; k0 < LOWD; k0 += 16) {
#pragma unroll
        for (int i = 0; i < 2; i++) {
            int f = tx + i * 256;
            int r = f >> 2;
            int kc = (f & 3) << 2;
            int gr = row0 + r;
            float4 v = make_float4(0.f, 0.f, 0.f, 0.f);
            if (gr < n) v = *(const float4*)&A[(size_t)gr * LOWD + k0 + kc];
            As[kc + 0][r] = v.x; As[kc + 1][r] = v.y; As[kc + 2][r] = v.z; As[kc + 3][r] = v.w;
        }
#pragma unroll
        for (int i = 0; i < 2; i++) {
            int f = tx + i * 256;
            int r = f >> 5;
            int cc = (f & 31) << 2;
            *(float4*)&Bs[r][cc] = *(const float4*)&g_W1l[(size_t)(k0 + r) * 128 + cc];
        }
        __syncthreads();
#pragma unroll
        for (int k = 0; k < 16; k++) {
            float a[8], b[8];
            *(float4*)&a[0] = *(const float4*)&As[k][trow * 8];
            *(float4*)&a[4] = *(const float4*)&As[k][trow * 8 + 4];
            *(float4*)&b[0] = *(const float4*)&Bs[k][tcol * 8];
            *(float4*)&b[4] = *(const float4*)&Bs[k][tcol * 8 + 4];
#pragma unroll
            for (int i = 0; i < 8; i++)
#pragma unroll
                for (int j = 0; j < 8; j++) acc[i][j] += a[i] * b[j];
        }
        __syncthreads();
    }

    float cs[8], cq[8], c1v[8];
#pragma unroll
    for (int j = 0; j < 8; j++) { cs[j] = 0.f; cq[j] = 0.f; c1v[j] = g_c1l[tcol * 8 + j]; }

    __half* zt = g_Ztl + (size_t)blockIdx.x * 16384;
    const int chunk = tcol >> 2;
    const uint32_t unit = (uint32_t)(tcol & 3) * 16;
#pragma unroll
    for (int i = 0; i < 8; i++) {
        int rloc = trow * 8 + i;
        int gr = row0 + rloc;
        float z[8];
#pragma unroll
        for (int j = 0; j < 8; j++) {
            float v = acc[i][j] + c1v[j];
            z[j] = v > 0.f ? v : 0.f;
        }
        if (gr < n) {
#pragma unroll
            for (int j = 0; j < 8; j++) { cs[j] += z[j]; cq[j] += z[j] * z[j]; }
        }
        __half2 p0 = __floats2half2_rn(z[0], z[1]);
        __half2 p1 = __floats2half2_rn(z[2], z[3]);
        __half2 p2 = __floats2half2_rn(z[4], z[5]);
        __half2 p3 = __floats2half2_rn(z[6], z[7]);
        uint32_t bo = (uint32_t)chunk * 8192 + (uint32_t)rloc * 64 +
                      (unit ^ ((((uint32_t)rloc >> 1) & 3u) << 4));
        *(uint4*)((char*)zt + bo) = make_uint4(h2u(p0), h2u(p1), h2u(p2), h2u(p3));
    }
    __syncthreads();
#pragma unroll
    for (int j = 0; j < 8; j++) As[trow][tcol * 8 + j] = cs[j];
    __syncthreads();
    if (tx < 128) {
        float s = 0.f;
#pragma unroll
        for (int r = 0; r < 16; r++) s += As[r][tx];
        atomicAdd(&g_sum2[EMB + tx], s);
    }
    __syncthreads();
#pragma unroll
    for (int j = 0; j < 8; j++) As[trow][tcol * 8 + j] = cq[j];
    __syncthreads();
    if (tx < 128) {
        float s = 0.f;
#pragma unroll
        for (int r = 0; r < 16; r++) s += As[r][tx];
        atomicAdd(&g_ssq2[EMB + tx], s);
    }
}

// ---------------- 8: finalize BN2 ----------------
__global__ void finalize2_kernel(const float* __restrict__ gh, const float* __restrict__ bh,
                                 const float* __restrict__ gl, const float* __restrict__ bl,
                                 float invn) {
    int i = threadIdx.x;
    const float* gg = (i < EMB) ? gh : gl;
    const float* bb = (i < EMB) ? bh : bl;
    int j = i & (EMB - 1);
    float m = g_sum2[i] * invn;
    float var = g_ssq2[i] * invn - m * m;
    float s = rsqrtf(var + BNEPS) * gg[j];
    g_scale2[i] = s;
    g_shift2[i] = bb[j] - m * s;
}

// ---------------- 9: fold BN2 into conv1 ----------------
__global__ void folds2_kernel(const float* __restrict__ W) {
    __shared__ float red[256];
    int b = blockIdx.x, tx = threadIdx.x;
    if (b < 128) {
        int i = b * 256 + tx;
        int k = i >> 7, nn = i & 127;
        float v = W[i] * g_scale2[k] * SC2;
        int c = k >> 5, kk = k & 31;
        uint32_t kb = (uint32_t)kk * 2;
        uint32_t sw = ((kb & 0x30u) ^ (((uint32_t)(nn >> 1) & 3u) << 4)) | (kb & 15u);
        g_Wc2h[(size_t)c * 4096 + (((uint32_t)nn * 64 + sw) >> 1)] = __float2half(v);
    } else {
        int k = b - 128;
        float s = g_shift2[tx] * W[(size_t)tx * 128 + k];
        red[tx] = s;
        __syncthreads();
        for (int off = 128; off; off >>= 1) {
            if (tx < off) red[tx] += red[tx + off];
            __syncthreads();
        }
        if (tx == 0) g_crow[k] = red[0];
    }
}

// ---------------- 10: GEMM 2 (fp16 mma, double-buffered) ----------------
__global__ void __launch_bounds__(256, 2) gemm2_kernel(int n) {
    __shared__ __align__(16) __half sA[2][128 * 32];
    __shared__ __align__(16) __half sB[2][128 * 32];

    const int tid = threadIdx.x;
    const int wid = tid >> 5, lane = tid & 31;
    const int wm = wid & 3, wn = wid >> 2;
    const int row0 = blockIdx.x * 128;

    const uint4* At = (const uint4*)(g_Zth + (size_t)blockIdx.x * 16384);
    const uint4* Al = (const uint4*)(g_Ztl + (size_t)blockIdx.x * 16384);
    const uint4* Bt = (const uint4*)g_Wc2h;

    const uint32_t aB0 = smem_u32(sA[0]), aB1 = smem_u32(sA[1]);
    const uint32_t bB0 = smem_u32(sB[0]), bB1 = smem_u32(sB[1]);
    const int lrA = lane & 15;
    const uint32_t lkA = ((uint32_t)(lane >> 4)) << 4;
    const uint32_t swA = (((uint32_t)(lrA >> 1) & 3u) << 4);
    const int lrB = (lane & 7) + ((lane >> 4) << 3);
    const uint32_t lkB = ((uint32_t)(lane & 8)) << 1;
    const uint32_t swB = (((uint32_t)(lrB >> 1) & 3u) << 4);

    float acc[2][8][4];
#pragma unroll
    for (int mt = 0; mt < 2; mt++)
#pragma unroll
        for (int j = 0; j < 8; j++)
#pragma unroll
            for (int q = 0; q < 4; q++) acc[mt][j][q] = 0.f;

    uint4 a4[2], b4[2];
    a4[0] = At[tid]; a4[1] = At[tid + 256];
    b4[0] = Bt[tid]; b4[1] = Bt[tid + 256];
    ((uint4*)sA[0])[tid] = a4[0]; ((uint4*)sA[0])[tid + 256] = a4[1];
    ((uint4*)sB[0])[tid] = b4[0]; ((uint4*)sB[0])[tid + 256] = b4[1];

    for (int c = 0; c < 8; c++) {
        __syncthreads();
        if (c + 1 < 8) {
            const uint4* src = (c + 1 < 4) ? (At + (size_t)(c + 1) * 512) : (Al + (size_t)(c - 3) * 512);
            a4[0] = src[tid]; a4[1] = src[tid + 256];
            b4[0] = Bt[(size_t)(c + 1) * 512 + tid]; b4[1] = Bt[(size_t)(c + 1) * 512 + tid + 256];
        }
        const uint32_t aB = (c & 1) ? aB1 : aB0;
        const uint32_t bB = (c & 1) ? bB1 : bB0;
#pragma unroll
        for (int ks = 0; ks < 2; ks++) {
            uint32_t af[2][4];
#pragma unroll
            for (int mt = 0; mt < 2; mt++) {
                uint32_t off = (uint32_t)(wm * 32 + mt * 16 + lrA) * 64 +
                               (((uint32_t)(ks * 32) + lkA) ^ swA);
                LDMX4(af[mt], aB + off);
            }
#pragma unroll
            for (int g4 = 0; g4 < 4; g4++) {
                uint32_t boff = (uint32_t)(wn * 64 + g4 * 16 + lrB) * 64 +
                                (((uint32_t)(ks * 32) + lkB) ^ swB);
                uint32_t bf[4];
                LDMX4(bf, bB + boff);
#pragma unroll
                for (int mt = 0; mt < 2; mt++) {
                    mma_f16(acc[mt][g4 * 2 + 0], af[mt], bf[0], bf[1]);
                    mma_f16(acc[mt][g4 * 2 + 1], af[mt], bf[2], bf[3]);
                }
            }
        }
        if (c + 1 < 8) {
            __half* dA = sA[(c + 1) & 1];
            __half* dB = sB[(c + 1) & 1];
            ((uint4*)dA)[tid] = a4[0]; ((uint4*)dA)[tid + 256] = a4[1];
            ((uint4*)dB)[tid] = b4[0]; ((uint4*)dB)[tid + 256] = b4[1];
        }
    }

    const int g = lane >> 2, t4 = lane & 3;
#pragma unroll
    for (int j = 0; j < 8; j++) {
        int col = wn * 64 + j * 8 + t4 * 2;
        float ca = g_crow[col], cb = g_crow[col + 1];
#pragma unroll
        for (int mt = 0; mt < 2; mt++)
#pragma unroll
            for (int h = 0; h < 2; h++) {
                int r = row0 + wm * 32 + mt * 16 + g + h * 8;
                if (r < n) {
                    float x0 = acc[mt][j][h * 2 + 0] * SC2I + ca;
                    float x1 = acc[mt][j][h * 2 + 1] * SC2I + cb;
                    *(__half2*)&g_XWh[(size_t)r * 128 + col] = __floats2half2_rn(x0, x1);
                }
            }
    }
}

// ---------------- graph machinery ----------------
__device__ __forceinline__ int edge_at(const void* edge, int e, int which_row, int i) {
    if (g_is64) {
        const long long* p = (const long long*)edge;
        return (int)p[(size_t)which_row * e + i];
    } else {
        const int* p = (const int*)edge;
        return p[(size_t)which_row * e + i];
    }
}

__global__ void deg_kernel(const void* __restrict__ edge, int e) {
    for (int i = blockIdx.x * blockDim.x + threadIdx.x; i < e; i += gridDim.x * blockDim.x) {
        int d = edge_at(edge, e, 1, i);
        atomicAdd(&g_deg[d], 1);
    }
}

// scan + dinv fused (single block, warp-shuffle scan)
__global__ void scan_kernel(int n) {
    __shared__ int wsum[32];
    __shared__ int s_carry;
    int tx = threadIdx.x, lane = tx & 31, wid = tx >> 5;
    if (tx == 0) { s_carry = 0; g_rowoff[0] = 0; }
    __syncthreads();
    for (int base = 0; base < n; base += 1024) {
        int i = base + tx;
        int v = (i < n) ? g_deg[i] : 0;
        if (i < n) g_dinv[i] = rsqrtf((float)(v + 1));
        int inc = v;
#pragma unroll
        for (int off = 1; off < 32; off <<= 1) {
            int t = __shfl_up_sync(0xffffffffu, inc, off);
            if (lane >= off) inc += t;
        }
        if (lane == 31) wsum[wid] = inc;
        __syncthreads();
        if (wid == 0) {
            int w = wsum[lane];
            int wi = w;
#pragma unroll
            for (int off = 1; off < 32; off <<= 1) {
                int t = __shfl_up_sync(0xffffffffu, wi, off);
                if (lane >= off) wi += t;
            }
            wsum[lane] = wi - w;
        }
        __syncthreads();
        int incl = inc + wsum[wid] + s_carry;
        if (i < n) {
            g_rowoff[i + 1] = incl;
            g_cursor[i] = incl - v;
        }
        __syncthreads();
        if (tx == 1023) s_carry = incl;
        __syncthreads();
    }
}

__global__ void fill_kernel(const void* __restrict__ edge, int e) {
    for (int i = blockIdx.x * blockDim.x + threadIdx.x; i < e; i += gridDim.x * blockDim.x) {
        int d = edge_at(edge, e, 1, i);
        int s = edge_at(edge, e, 0, i);
        int p = atomicAdd(&g_cursor[d], 1);
        g_csr[p] = s;
    }
}

// ---------------- gather + tanh + classifier + log_softmax ----------------
__global__ void gather_kernel(const float* __restrict__ convb, const float* __restrict__ clsW,
                              const float* __restrict__ clsb, float* __restrict__ out, int n) {
    int gw = (blockIdx.x * blockDim.x + threadIdx.x) >> 5;
    int lane = threadIdx.x & 31;
    if (gw >= n) return;
    const float di = g_dinv[gw];
    const uint2* xw2 = (const uint2*)g_XWh;

    uint2 u = xw2[(size_t)gw * 32 + lane];
    float2 f0 = __half22float2(*(__half2*)&u.x);
    float2 f1 = __half22float2(*(__half2*)&u.y);
    float ax = f0.x * di, ay = f0.y * di, az = f1.x * di, aw = f1.y * di;

    int beg = g_rowoff[gw], end = g_rowoff[gw + 1];
    for (int j = beg; j < end; j++) {
        int s = g_csr[j];
        float w = g_dinv[s];
        uint2 v = xw2[(size_t)s * 32 + lane];
        float2 v0 = __half22float2(*(__half2*)&v.x);
        float2 v1 = __half22float2(*(__half2*)&v.y);
        ax += v0.x * w; ay += v0.y * w; az += v1.x * w; aw += v1.y * w;
    }
    float4 cb = ((const float4*)convb)[lane];
    float h0 = tanhf(ax * di + cb.x);
    float h1 = tanhf(ay * di + cb.y);
    float h2 = tanhf(az * di + cb.z);
    float h3 = tanhf(aw * di + cb.w);

    int c0 = lane * 4;
    float lo[OUTC];
#pragma unroll
    for (int o = 0; o < OUTC; o++) {
        lo[o] = h0 * clsW[(size_t)c0 * OUTC + o]
              + h1 * clsW[(size_t)(c0 + 1) * OUTC + o]
              + h2 * clsW[(size_t)(c0 + 2) * OUTC + o]
              + h3 * clsW[(size_t)(c0 + 3) * OUTC + o];
    }
#pragma unroll
    for (int off = 16; off; off >>= 1)
#pragma unroll
        for (int o = 0; o < OUTC; o++)
            lo[o] += __shfl_xor_sync(0xffffffffu, lo[o], off);

    if (lane == 0) {
        float m = -1e30f;
#pragma unroll
        for (int o = 0; o < OUTC; o++) { lo[o] += clsb[o]; m = fmaxf(m, lo[o]); }
        float s = 0.f;
#pragma unroll
        for (int o = 0; o < OUTC; o++) s += expf(lo[o] - m);
        float lse = m + logf(s);
#pragma unroll
        for (int o = 0; o < OUTC; o++) out[(size_t)gw * OUTC + o] = lo[o] - lse;
    }
}

// ---------------- launch ----------------
extern "C" void kernel_launch(void* const* d_in, const int* in_sizes, int n_in,
                              void* d_out, int out_size) {
    const float* low_x      = (const float*)d_in[1];
    const float* cov_x      = (const float*)d_in[2];
    const void*  edge       = d_in[3];
    const float* bn_low_g   = (const float*)d_in[4];
    const float* bn_low_b   = (const float*)d_in[5];
    const float* bn_high_g  = (const float*)d_in[6];
    const float* bn_high_b  = (const float*)d_in[7];
    const float* lin_low_W  = (const float*)d_in[8];
    const float* lin_low_b  = (const float*)d_in[9];
    const float* mlp_low_g  = (const float*)d_in[10];
    const float* mlp_low_b  = (const float*)d_in[11];
    const float* lin_high_W = (const float*)d_in[12];
    const float* lin_high_b = (const float*)d_in[13];
    const float* mlp_high_g = (const float*)d_in[14];
    const float* mlp_high_b = (const float*)d_in[15];
    const float* conv1_W    = (const float*)d_in[16];
    const float* conv1_b    = (const float*)d_in[17];
    const float* cls_W      = (const float*)d_in[18];
    const float* cls_b      = (const float*)d_in[19];

    int n = in_sizes[1] / LOWD;
    int e = in_sizes[3] / 2;
    float invn = 1.f / (float)n;
    int nblk = (n + 127) / 128;

    // 1
    zero_detect_kernel<<<(n + 255) / 256, 256>>>(n, (const int*)edge, e);
    // 2-3: input BN stats
    colstats4_kernel<<<dim3(HIGHD / 1024, 256), 256>>>(cov_x, n);
    colstats_low_kernel<<<128, 256>>>(low_x, n);
    // 4: finalize BN1
    finalize1_kernel<<<(HIGHD + LOWD + 255) / 256, 256>>>(bn_high_g, bn_high_b, bn_low_g, bn_low_b, invn);
    // 5: fold BN1 into linears (all fused)
    folds1_kernel<<<2336, 256>>>(lin_high_W, lin_high_b, lin_low_W, lin_low_b);
    // 6: high GEMM  (profiled launch)
    gemm_mma_kernel<<<nblk, 256>>>(cov_x, n);
    // 7: low GEMM
    gemm_relu_stats_kernel<<<nblk, 256>>>(low_x, n);
    // 8: finalize BN2
    finalize2_kernel<<<1, 256>>>(mlp_high_g, mlp_high_b, mlp_low_g, mlp_low_b, invn);
    // 9: fold BN2 into conv1
    folds2_kernel<<<256, 256>>>(conv1_W);
    // 10: xw GEMM
    gemm2_kernel<<<nblk, 256>>>(n);
    // 11-13: graph build
    deg_kernel<<<2048, 256>>>(edge, e);
    scan_kernel<<<1, 1024>>>(n);
    fill_kernel<<<2048, 256>>>(edge, e);
    // 14: aggregate + epilogue
    gather_kernel<<<(n * 32 + 255) / 256, 256>>>(conv1_b, cls_W, cls_b, (float*)d_out, n);
}